// round 5
// baseline (speedup 1.0000x reference)
#include <cuda_runtime.h>
#include <cuda_bf16.h>
#include <math.h>
#include <stdint.h>

#define Bb   8
#define Ss   2048
#define Dd   256
#define Hh   8
#define DKk  32
#define DFFf 1024
#define Ll   5
#define Mm   (Bb*Ss)   // 16384 rows

// ---------------- scratch (device globals; no allocation allowed) ----------
__device__ float g_X [(size_t)Mm*Dd];
__device__ float g_Tb[(size_t)Mm*Dd];
__device__ __align__(16) uint16_t g_Xh[(size_t)Mm*Dd],  g_Xl[(size_t)Mm*Dd];
__device__ __align__(16) uint16_t g_Qh[(size_t)Mm*Dd],  g_Ql[(size_t)Mm*Dd];
__device__ __align__(16) uint16_t g_Kh[(size_t)Mm*Dd],  g_Kl[(size_t)Mm*Dd];
__device__ __align__(16) uint16_t g_Vh[(size_t)Mm*Dd],  g_Vl[(size_t)Mm*Dd];
__device__ __align__(16) uint16_t g_Ch[(size_t)Mm*Dd],  g_Cl[(size_t)Mm*Dd];
__device__ __align__(16) uint16_t g_Hh[(size_t)Mm*DFFf], g_Hl[(size_t)Mm*DFFf];
// pre-split weights (all layers)
__device__ __align__(16) uint16_t g_Wqh[Ll*Dd*Dd],  g_Wql[Ll*Dd*Dd];
__device__ __align__(16) uint16_t g_Wkh[Ll*Dd*Dd],  g_Wkl[Ll*Dd*Dd];
__device__ __align__(16) uint16_t g_Wvh[Ll*Dd*Dd],  g_Wvl[Ll*Dd*Dd];
__device__ __align__(16) uint16_t g_Woh[Ll*Dd*Dd],  g_Wol[Ll*Dd*Dd];
__device__ __align__(16) uint16_t g_W1h[Ll*Dd*DFFf], g_W1l[Ll*Dd*DFFf];
__device__ __align__(16) uint16_t g_W2h[Ll*DFFf*Dd], g_W2l[Ll*DFFf*Dd];

// ======================= warp-MMA helpers ===================================
__device__ __forceinline__ uint32_t cvta_s(const void* p) {
    return (uint32_t)__cvta_generic_to_shared(p);
}
__device__ __forceinline__ void ldsm4(uint32_t r[4], uint32_t a) {
    asm volatile("ldmatrix.sync.aligned.m8n8.x4.shared.b16 {%0,%1,%2,%3}, [%4];"
        : "=r"(r[0]), "=r"(r[1]), "=r"(r[2]), "=r"(r[3]) : "r"(a));
}
__device__ __forceinline__ void ldsm4t(uint32_t r[4], uint32_t a) {
    asm volatile("ldmatrix.sync.aligned.m8n8.x4.trans.shared.b16 {%0,%1,%2,%3}, [%4];"
        : "=r"(r[0]), "=r"(r[1]), "=r"(r[2]), "=r"(r[3]) : "r"(a));
}
__device__ __forceinline__ void mma_bf(float c[4], const uint32_t a[4],
                                       const uint32_t b[2]) {
    asm volatile(
        "mma.sync.aligned.m16n8k16.row.col.f32.bf16.bf16.f32 "
        "{%0,%1,%2,%3},{%4,%5,%6,%7},{%8,%9},{%0,%1,%2,%3};"
        : "+f"(c[0]), "+f"(c[1]), "+f"(c[2]), "+f"(c[3])
        : "r"(a[0]), "r"(a[1]), "r"(a[2]), "r"(a[3]), "r"(b[0]), "r"(b[1]));
}
// pack two floats -> bf16x2 (x -> low half)
__device__ __forceinline__ uint32_t pack_bf(float x, float y) {
    uint32_t r;
    asm("cvt.rn.bf16x2.f32 %0, %1, %2;" : "=r"(r) : "f"(y), "f"(x));
    return r;
}
__device__ __forceinline__ void split_pair(float x, float y,
                                           uint32_t& hi, uint32_t& lo) {
    hi = pack_bf(x, y);
    float hx = __uint_as_float(hi << 16);
    float hy = __uint_as_float(hi & 0xFFFF0000u);
    lo = pack_bf(x - hx, y - hy);
}

// ---------------- converters ------------------------------------------------
__global__ void split_w(const float* __restrict__ in, uint16_t* __restrict__ hi,
                        uint16_t* __restrict__ lo, int n2)
{
    for (int i = blockIdx.x * blockDim.x + threadIdx.x; i < n2;
         i += gridDim.x * blockDim.x) {
        float2 v = ((const float2*)in)[i];
        uint32_t h, l;
        split_pair(v.x, v.y, h, l);
        *(uint32_t*)&hi[2*i] = h;
        *(uint32_t*)&lo[2*i] = l;
    }
}
__global__ void src_conv(const float* __restrict__ in, float* __restrict__ of,
                         uint16_t* __restrict__ hi, uint16_t* __restrict__ lo,
                         int n2)
{
    for (int i = blockIdx.x * blockDim.x + threadIdx.x; i < n2;
         i += gridDim.x * blockDim.x) {
        float2 v = ((const float2*)in)[i];
        ((float2*)of)[i] = v;
        uint32_t h, l;
        split_pair(v.x, v.y, h, l);
        *(uint32_t*)&hi[2*i] = h;
        *(uint32_t*)&lo[2*i] = l;
    }
}

// ============== pure-bf16 tensor-core GEMM ==================================
// C = A @ W + bias (+GELU). Block 128x128, ktile 32, 8 warps (4M x 2N), warp 32x64.
#define APITCH 40
#define BPITCH 136

__global__ __launch_bounds__(256) void gemm_bf(
    const uint16_t* __restrict__ Ah_, const uint16_t* __restrict__ Al_,
    const uint16_t* __restrict__ Wh_, const uint16_t* __restrict__ Wl_,
    const float* __restrict__ bias,
    float* __restrict__ Cf, uint16_t* __restrict__ Ch_, uint16_t* __restrict__ Cl_,
    int N, int K, int act)
{
    __shared__ __align__(16) uint16_t Ahs[128*APITCH], Als[128*APITCH];
    __shared__ __align__(16) uint16_t Bhs[32*BPITCH],  Bls[32*BPITCH];

    const int tid  = threadIdx.x;
    const int lane = tid & 31, wid = tid >> 5;
    const int wm = wid & 3, wn = wid >> 2;
    const int m0 = blockIdx.y * 128, n0 = blockIdx.x * 128;

    const uint32_t aAh = cvta_s(Ahs), aAl = cvta_s(Als);
    const uint32_t aBh = cvta_s(Bhs), aBl = cvta_s(Bls);

    float acc[2][8][4];
#pragma unroll
    for (int i = 0; i < 2; i++)
#pragma unroll
        for (int j = 0; j < 8; j++)
#pragma unroll
            for (int u = 0; u < 4; u++) acc[i][j][u] = 0.f;

    for (int kt = 0; kt < K; kt += 32) {
        if (kt) __syncthreads();
        // A tiles: 128x32 bf16 x2 tensors (512 uint4 each)
#pragma unroll
        for (int j = 0; j < 2; j++) {
            const int idx = tid + j * 256;
            const int r = idx >> 2, c8 = idx & 3;
            const size_t go = (size_t)(m0 + r) * K + kt + c8 * 8;
            *(uint4*)&Ahs[r*APITCH + c8*8] = *(const uint4*)&Ah_[go];
            *(uint4*)&Als[r*APITCH + c8*8] = *(const uint4*)&Al_[go];
        }
        // B tiles: 32x128 bf16 x2
#pragma unroll
        for (int j = 0; j < 2; j++) {
            const int idx = tid + j * 256;
            const int r = idx >> 4, c8 = idx & 15;
            const size_t go = (size_t)(kt + r) * N + n0 + c8 * 8;
            *(uint4*)&Bhs[r*BPITCH + c8*8] = *(const uint4*)&Wh_[go];
            *(uint4*)&Bls[r*BPITCH + c8*8] = *(const uint4*)&Wl_[go];
        }
        __syncthreads();

#pragma unroll
        for (int kb = 0; kb < 2; kb++) {
            uint32_t ah[2][4], al[2][4];
#pragma unroll
            for (int i = 0; i < 2; i++) {
                const int row = wm * 32 + i * 16 + (lane & 15);
                const uint32_t byt =
                    (uint32_t)(row * APITCH + kb * 16 + ((lane >> 4) << 3)) * 2;
                ldsm4(ah[i], aAh + byt);
                ldsm4(al[i], aAl + byt);
            }
            const int mmm = lane >> 3, rr = lane & 7;
            const int kk = kb * 16 + ((mmm & 1) << 3) + rr;
#pragma unroll
            for (int jp = 0; jp < 4; jp++) {
                uint32_t bh4[4], bl4[4];
                const int nn = wn * 64 + jp * 16 + ((mmm >> 1) << 3);
                const uint32_t byt = (uint32_t)(kk * BPITCH + nn) * 2;
                ldsm4t(bh4, aBh + byt);
                ldsm4t(bl4, aBl + byt);
#pragma unroll
                for (int i = 0; i < 2; i++) {
                    mma_bf(acc[i][2*jp],   ah[i], bh4);
                    mma_bf(acc[i][2*jp],   ah[i], bl4);
                    mma_bf(acc[i][2*jp],   al[i], bh4);
                    mma_bf(acc[i][2*jp+1], ah[i], bh4 + 2);
                    mma_bf(acc[i][2*jp+1], ah[i], bl4 + 2);
                    mma_bf(acc[i][2*jp+1], al[i], bh4 + 2);
                }
            }
        }
    }

    // ---- epilogue ----
    const int gid = lane >> 2, tig = lane & 3;
#pragma unroll
    for (int i = 0; i < 2; i++) {
        const int r0 = m0 + wm * 32 + i * 16 + gid;
#pragma unroll
        for (int j = 0; j < 8; j++) {
            const int col = n0 + wn * 64 + j * 8 + tig * 2;
            const float b0 = bias[col], b1 = bias[col + 1];
            float x0 = acc[i][j][0] + b0, x1 = acc[i][j][1] + b1;
            float x2 = acc[i][j][2] + b0, x3 = acc[i][j][3] + b1;
            if (act) {
                x0 = 0.5f * x0 * (1.f + erff(x0 * 0.70710678118654752f));
                x1 = 0.5f * x1 * (1.f + erff(x1 * 0.70710678118654752f));
                x2 = 0.5f * x2 * (1.f + erff(x2 * 0.70710678118654752f));
                x3 = 0.5f * x3 * (1.f + erff(x3 * 0.70710678118654752f));
            }
            if (Cf) {
                *(float2*)(Cf + (size_t)r0 * N + col)       = make_float2(x0, x1);
                *(float2*)(Cf + (size_t)(r0 + 8) * N + col) = make_float2(x2, x3);
            }
            if (Ch_) {
                uint32_t h, l;
                split_pair(x0, x1, h, l);
                *(uint32_t*)&Ch_[(size_t)r0 * N + col] = h;
                *(uint32_t*)&Cl_[(size_t)r0 * N + col] = l;
                split_pair(x2, x3, h, l);
                *(uint32_t*)&Ch_[(size_t)(r0 + 8) * N + col] = h;
                *(uint32_t*)&Cl_[(size_t)(r0 + 8) * N + col] = l;
            }
        }
    }
}

// ============== bf16x3 tensor-core flash attention ==========================
// grid (S/64, H, B), 128 threads (4 warps). Warp w owns q rows w*16..w*16+15.
#define KPITCH 40
#define SPITCH 68

__global__ __launch_bounds__(128) void attn_mma(
    const uint16_t* __restrict__ Qh_, const uint16_t* __restrict__ Ql_,
    const uint16_t* __restrict__ Kh_, const uint16_t* __restrict__ Kl_,
    const uint16_t* __restrict__ Vh_, const uint16_t* __restrict__ Vl_,
    const float* __restrict__ sph,
    uint16_t* __restrict__ Oh_, uint16_t* __restrict__ Ol_)
{
    __shared__ __align__(16) uint16_t Khs[64*KPITCH], Kls[64*KPITCH];
    __shared__ __align__(16) uint16_t Vhs[64*KPITCH], Vls[64*KPITCH];
    __shared__ __align__(16) float    Bs [64*SPITCH];

    const int tid  = threadIdx.x;
    const int lane = tid & 31, w = tid >> 5;
    const int gid = lane >> 2, tig = lane & 3;
    const int qb = blockIdx.x, h = blockIdx.y, b = blockIdx.z;
    const int q0 = qb * 64;

    const uint32_t aKh = cvta_s(Khs), aKl = cvta_s(Kls);
    const uint32_t aVh = cvta_s(Vhs), aVl = cvta_s(Vls);

    // ---- stage Q into K buffers, extract fragments once ----
#pragma unroll
    for (int j = 0; j < 2; j++) {
        const int idx = tid + j * 128;            // 256 uint4 per tensor
        const int r = idx >> 2, c8 = idx & 3;
        const size_t go = (size_t)(b*Ss + q0 + r) * Dd + h * 32 + c8 * 8;
        *(uint4*)&Khs[r*KPITCH + c8*8] = *(const uint4*)&Qh_[go];
        *(uint4*)&Kls[r*KPITCH + c8*8] = *(const uint4*)&Ql_[go];
    }
    __syncthreads();
    uint32_t qh[2][4], ql[2][4];
#pragma unroll
    for (int kb = 0; kb < 2; kb++) {
        const int row = w * 16 + (lane & 15);
        const uint32_t byt =
            (uint32_t)(row * KPITCH + kb * 16 + ((lane >> 4) << 3)) * 2;
        ldsm4(qh[kb], aKh + byt);
        ldsm4(ql[kb], aKl + byt);
    }
    __syncthreads();

    float m[2] = {-INFINITY, -INFINITY}, l[2] = {0.f, 0.f};
    float o[4][4];
#pragma unroll
    for (int jd = 0; jd < 4; jd++)
#pragma unroll
        for (int u = 0; u < 4; u++) o[jd][u] = 0.f;

    const float* sphb = sph + (size_t)b*Ss*Ss + (size_t)q0*Ss;
    const float sc = 0.17677669529663687f;        // 1/sqrt(32)

    for (int k0 = 0; k0 < Ss; k0 += 64) {
        // ---- K/V tiles (bf16 hi/lo) + bias tile ----
#pragma unroll
        for (int j = 0; j < 2; j++) {
            const int idx = tid + j * 128;
            const int r = idx >> 2, c8 = idx & 3;
            const size_t go = (size_t)(b*Ss + k0 + r) * Dd + h * 32 + c8 * 8;
            const int so = r*KPITCH + c8*8;
            *(uint4*)&Khs[so] = *(const uint4*)&Kh_[go];
            *(uint4*)&Kls[so] = *(const uint4*)&Kl_[go];
            *(uint4*)&Vhs[so] = *(const uint4*)&Vh_[go];
            *(uint4*)&Vls[so] = *(const uint4*)&Vl_[go];
        }
#pragma unroll
        for (int j = 0; j < 8; j++) {
            const int idx = tid + j * 128;        // 1024 float4
            const int r = idx >> 4, c4 = idx & 15;
            *(float4*)&Bs[r * SPITCH + c4 * 4] =
                *(const float4*)(sphb + (size_t)r * Ss + k0 + c4 * 4);
        }
        __syncthreads();

        // ---- S = Q K^T ----
        float s[8][4];
#pragma unroll
        for (int j = 0; j < 8; j++)
#pragma unroll
            for (int u = 0; u < 4; u++) s[j][u] = 0.f;

        const int mmm = lane >> 3, rr = lane & 7;
#pragma unroll
        for (int kb = 0; kb < 2; kb++) {
            const int kk = kb * 16 + ((mmm & 1) << 3);
#pragma unroll
            for (int jp = 0; jp < 4; jp++) {
                uint32_t kh4[4], kl4[4];
                const int nn = jp * 16 + ((mmm >> 1) << 3) + rr;
                const uint32_t byt = (uint32_t)(nn * KPITCH + kk) * 2;
                ldsm4(kh4, aKh + byt);
                ldsm4(kl4, aKl + byt);
                mma_bf(s[2*jp],   qh[kb], kh4);
                mma_bf(s[2*jp],   qh[kb], kl4);
                mma_bf(s[2*jp],   ql[kb], kh4);
                mma_bf(s[2*jp+1], qh[kb], kh4 + 2);
                mma_bf(s[2*jp+1], qh[kb], kl4 + 2);
                mma_bf(s[2*jp+1], ql[kb], kh4 + 2);
            }
        }

        // ---- scale + bias + online softmax ----
        float rmax0 = -INFINITY, rmax1 = -INFINITY;
#pragma unroll
        for (int j = 0; j < 8; j++) {
            const int col = j * 8 + tig * 2;
            float2 b0 = *(float2*)&Bs[(w*16 + gid)     * SPITCH + col];
            float2 b1 = *(float2*)&Bs[(w*16 + gid + 8) * SPITCH + col];
            s[j][0] = fmaf(s[j][0], sc, b0.x);
            s[j][1] = fmaf(s[j][1], sc, b0.y);
            s[j][2] = fmaf(s[j][2], sc, b1.x);
            s[j][3] = fmaf(s[j][3], sc, b1.y);
            rmax0 = fmaxf(rmax0, fmaxf(s[j][0], s[j][1]));
            rmax1 = fmaxf(rmax1, fmaxf(s[j][2], s[j][3]));
        }
        rmax0 = fmaxf(rmax0, __shfl_xor_sync(0xffffffffu, rmax0, 1));
        rmax0 = fmaxf(rmax0, __shfl_xor_sync(0xffffffffu, rmax0, 2));
        rmax1 = fmaxf(rmax1, __shfl_xor_sync(0xffffffffu, rmax1, 1));
        rmax1 = fmaxf(rmax1, __shfl_xor_sync(0xffffffffu, rmax1, 2));

        const float mn0 = fmaxf(m[0], rmax0), mn1 = fmaxf(m[1], rmax1);
        const float al0 = __expf(m[0] - mn0), al1 = __expf(m[1] - mn1);
        m[0] = mn0; m[1] = mn1;

        float ps0 = 0.f, ps1 = 0.f;
        uint32_t ph[4][4], pl[4][4];
#pragma unroll
        for (int j = 0; j < 8; j++) {
            float p0 = __expf(s[j][0] - mn0), p1 = __expf(s[j][1] - mn0);
            float p2 = __expf(s[j][2] - mn1), p3 = __expf(s[j][3] - mn1);
            ps0 += p0 + p1; ps1 += p2 + p3;
            uint32_t hA, lA, hB, lB;
            split_pair(p0, p1, hA, lA);
            split_pair(p2, p3, hB, lB);
            const int kb = j >> 1;
            if (!(j & 1)) { ph[kb][0] = hA; pl[kb][0] = lA;
                            ph[kb][1] = hB; pl[kb][1] = lB; }
            else          { ph[kb][2] = hA; pl[kb][2] = lA;
                            ph[kb][3] = hB; pl[kb][3] = lB; }
        }
        ps0 += __shfl_xor_sync(0xffffffffu, ps0, 1);
        ps0 += __shfl_xor_sync(0xffffffffu, ps0, 2);
        ps1 += __shfl_xor_sync(0xffffffffu, ps1, 1);
        ps1 += __shfl_xor_sync(0xffffffffu, ps1, 2);
        l[0] = l[0] * al0 + ps0;
        l[1] = l[1] * al1 + ps1;
#pragma unroll
        for (int jd = 0; jd < 4; jd++) {
            o[jd][0] *= al0; o[jd][1] *= al0;
            o[jd][2] *= al1; o[jd][3] *= al1;
        }

        // ---- O += P V ----
#pragma unroll
        for (int kb = 0; kb < 4; kb++) {
            const int kk = kb * 16 + ((mmm & 1) << 3) + rr;
#pragma unroll
            for (int jp = 0; jp < 2; jp++) {
                uint32_t vh4[4], vl4[4];
                const int dd = jp * 16 + ((mmm >> 1) << 3);
                const uint32_t byt = (uint32_t)(kk * KPITCH + dd) * 2;
                ldsm4t(vh4, aVh + byt);
                ldsm4t(vl4, aVl + byt);
                mma_bf(o[2*jp],   ph[kb], vh4);
                mma_bf(o[2*jp],   ph[kb], vl4);
                mma_bf(o[2*jp],   pl[kb], vh4);
                mma_bf(o[2*jp+1], ph[kb], vh4 + 2);
                mma_bf(o[2*jp+1], ph[kb], vl4 + 2);
                mma_bf(o[2*jp+1], pl[kb], vh4 + 2);
            }
        }
        __syncthreads();
    }

    const float inv0 = 1.f / l[0], inv1 = 1.f / l[1];
    const int r0 = b*Ss + q0 + w*16 + gid;
#pragma unroll
    for (int jd = 0; jd < 4; jd++) {
        const int col = h * 32 + jd * 8 + tig * 2;
        uint32_t hh, ll2;
        split_pair(o[jd][0] * inv0, o[jd][1] * inv0, hh, ll2);
        *(uint32_t*)&Oh_[(size_t)r0 * Dd + col] = hh;
        *(uint32_t*)&Ol_[(size_t)r0 * Dd + col] = ll2;
        split_pair(o[jd][2] * inv1, o[jd][3] * inv1, hh, ll2);
        *(uint32_t*)&Oh_[(size_t)(r0 + 8) * Dd + col] = hh;
        *(uint32_t*)&Ol_[(size_t)(r0 + 8) * Dd + col] = ll2;
    }
}

// ---------------- fused residual + LayerNorm (+ bf16 mirrors) ---------------
__global__ __launch_bounds__(256) void add_ln(
    const float* __restrict__ x, const float* __restrict__ s,
    const float* __restrict__ g, const float* __restrict__ bb,
    float* __restrict__ out, uint16_t* __restrict__ oh, uint16_t* __restrict__ ol)
{
    const int row = blockIdx.x;
    const int t   = threadIdx.x;
    const size_t idx = (size_t)row * Dd + t;
    const float v = x[idx] + s[idx];

    float sum = v, sq = v * v;
#pragma unroll
    for (int o = 16; o; o >>= 1) {
        sum += __shfl_xor_sync(0xffffffffu, sum, o);
        sq  += __shfl_xor_sync(0xffffffffu, sq,  o);
    }
    __shared__ float ssum[8], ssq[8];
    const int w = t >> 5, lane = t & 31;
    if (lane == 0) { ssum[w] = sum; ssq[w] = sq; }
    __syncthreads();
    if (w == 0) {
        float a = (lane < 8) ? ssum[lane] : 0.f;
        float c = (lane < 8) ? ssq[lane]  : 0.f;
#pragma unroll
        for (int o = 4; o; o >>= 1) {
            a += __shfl_xor_sync(0xffffffffu, a, o);
            c += __shfl_xor_sync(0xffffffffu, c, o);
        }
        if (lane == 0) { ssum[0] = a; ssq[0] = c; }
    }
    __syncthreads();
    const float mu  = ssum[0] * (1.f / Dd);
    const float var = ssq[0]  * (1.f / Dd) - mu * mu;
    const float y = (v - mu) * rsqrtf(var + 1e-5f) * g[t] + bb[t];
    out[idx] = y;
    if (oh) {
        __nv_bfloat16 hb = __float2bfloat16(y);
        float hf = __bfloat162float(hb);
        __nv_bfloat16 lb = __float2bfloat16(y - hf);
        oh[idx] = __bfloat16_as_ushort(hb);
        ol[idx] = __bfloat16_as_ushort(lb);
    }
}

// ---------------- driver ----------------------------------------------------
extern "C" void kernel_launch(void* const* d_in, const int* in_sizes, int n_in,
                              void* d_out, int out_size)
{
    const float* src = (const float*)d_in[0];
    const float* sph = (const float*)d_in[1];
    const float* Wq  = (const float*)d_in[2];
    const float* bq  = (const float*)d_in[3];
    const float* Wk  = (const float*)d_in[4];
    const float* bk  = (const float*)d_in[5];
    const float* Wv  = (const float*)d_in[6];
    const float* bv  = (const float*)d_in[7];
    const float* Wo  = (const float*)d_in[8];
    const float* bo  = (const float*)d_in[9];
    const float* W1  = (const float*)d_in[10];
    const float* b1  = (const float*)d_in[11];
    const float* W2  = (const float*)d_in[12];
    const float* b2  = (const float*)d_in[13];
    const float* g1  = (const float*)d_in[14];
    const float* be1 = (const float*)d_in[15];
    const float* g2  = (const float*)d_in[16];
    const float* be2 = (const float*)d_in[17];
    float* out = (float*)d_out;

    float *X, *Tb;
    uint16_t *Xh,*Xl,*Qh,*Ql,*Kh,*Kl,*Vh,*Vl,*Ch,*Cl,*Hhp,*Hlp;
    uint16_t *Wqh,*Wql,*Wkh,*Wkl,*Wvh,*Wvl,*Woh,*Wol,*W1h,*W1l,*W2h,*W2l;
    cudaGetSymbolAddress((void**)&X,  g_X);
    cudaGetSymbolAddress((void**)&Tb, g_Tb);
    cudaGetSymbolAddress((void**)&Xh, g_Xh); cudaGetSymbolAddress((void**)&Xl, g_Xl);
    cudaGetSymbolAddress((void**)&Qh, g_Qh); cudaGetSymbolAddress((void**)&Ql, g_Ql);
    cudaGetSymbolAddress((void**)&Kh, g_Kh); cudaGetSymbolAddress((void**)&Kl, g_Kl);
    cudaGetSymbolAddress((void**)&Vh, g_Vh); cudaGetSymbolAddress((void**)&Vl, g_Vl);
    cudaGetSymbolAddress((void**)&Ch, g_Ch); cudaGetSymbolAddress((void**)&Cl, g_Cl);
    cudaGetSymbolAddress((void**)&Hhp, g_Hh); cudaGetSymbolAddress((void**)&Hlp, g_Hl);
    cudaGetSymbolAddress((void**)&Wqh, g_Wqh); cudaGetSymbolAddress((void**)&Wql, g_Wql);
    cudaGetSymbolAddress((void**)&Wkh, g_Wkh); cudaGetSymbolAddress((void**)&Wkl, g_Wkl);
    cudaGetSymbolAddress((void**)&Wvh, g_Wvh); cudaGetSymbolAddress((void**)&Wvl, g_Wvl);
    cudaGetSymbolAddress((void**)&Woh, g_Woh); cudaGetSymbolAddress((void**)&Wol, g_Wol);
    cudaGetSymbolAddress((void**)&W1h, g_W1h); cudaGetSymbolAddress((void**)&W1l, g_W1l);
    cudaGetSymbolAddress((void**)&W2h, g_W2h); cudaGetSymbolAddress((void**)&W2l, g_W2l);

    // one-time conversions (captured in the graph; deterministic)
    split_w<<<512, 256>>>(Wq, Wqh, Wql, Ll*Dd*Dd/2);
    split_w<<<512, 256>>>(Wk, Wkh, Wkl, Ll*Dd*Dd/2);
    split_w<<<512, 256>>>(Wv, Wvh, Wvl, Ll*Dd*Dd/2);
    split_w<<<512, 256>>>(Wo, Woh, Wol, Ll*Dd*Dd/2);
    split_w<<<1024, 256>>>(W1, W1h, W1l, Ll*Dd*DFFf/2);
    split_w<<<1024, 256>>>(W2, W2h, W2l, Ll*DFFf*Dd/2);
    src_conv<<<1024, 256>>>(src, X, Xh, Xl, Mm*Dd/2);

    const dim3 gD (Dd/128,   Mm/128);   // 2  x 128
    const dim3 gF1(DFFf/128, Mm/128);   // 8  x 128
    const dim3 gAt(Ss/64, Hh, Bb);      // 32 x 8 x 8

    for (int i = 0; i < Ll; i++) {
        const size_t od = (size_t)i*Dd*Dd, of1 = (size_t)i*Dd*DFFf,
                     of2 = (size_t)i*DFFf*Dd;

        gemm_bf<<<gD, 256>>>(Xh, Xl, Wqh+od, Wql+od, bq + i*Dd,
                             nullptr, Qh, Ql, Dd, Dd, 0);
        gemm_bf<<<gD, 256>>>(Xh, Xl, Wkh+od, Wkl+od, bk + i*Dd,
                             nullptr, Kh, Kl, Dd, Dd, 0);
        gemm_bf<<<gD, 256>>>(Xh, Xl, Wvh+od, Wvl+od, bv + i*Dd,
                             nullptr, Vh, Vl, Dd, Dd, 0);

        attn_mma<<<gAt, 128>>>(Qh, Ql, Kh, Kl, Vh, Vl, sph, Ch, Cl);

        gemm_bf<<<gD, 256>>>(Ch, Cl, Woh+od, Wol+od, bo + i*Dd,
                             Tb, nullptr, nullptr, Dd, Dd, 0);
        add_ln<<<Mm, Dd>>>(X, Tb, g1 + i*Dd, be1 + i*Dd, X, Xh, Xl);

        gemm_bf<<<gF1, 256>>>(Xh, Xl, W1h+of1, W1l+of1, b1 + i*DFFf,
                              nullptr, Hhp, Hlp, DFFf, Dd, 1);
        gemm_bf<<<gD, 256>>>(Hhp, Hlp, W2h+of2, W2l+of2, b2 + i*Dd,
                             Tb, nullptr, nullptr, Dd, DFFf, 0);
        if (i == Ll-1)
            add_ln<<<Mm, Dd>>>(X, Tb, g2 + i*Dd, be2 + i*Dd, out,
                               nullptr, nullptr);
        else
            add_ln<<<Mm, Dd>>>(X, Tb, g2 + i*Dd, be2 + i*Dd, X, Xh, Xl);
    }
}

// round 6
// speedup vs baseline: 1.2200x; 1.2200x over previous
#include <cuda_runtime.h>
#include <cuda_bf16.h>
#include <math.h>
#include <stdint.h>

#define Bb   8
#define Ss   2048
#define Dd   256
#define Hh   8
#define DKk  32
#define DFFf 1024
#define Ll   5
#define Mm   (Bb*Ss)   // 16384 rows

// ---------------- scratch (device globals; no allocation allowed) ----------
__device__ float g_X [(size_t)Mm*Dd];
__device__ float g_Tb[(size_t)Mm*Dd];
__device__ __align__(16) uint16_t g_Xh[(size_t)Mm*Dd],  g_Xl[(size_t)Mm*Dd];
__device__ __align__(16) uint16_t g_Qh[(size_t)Mm*Dd],  g_Ql[(size_t)Mm*Dd];
__device__ __align__(16) uint16_t g_Kh[(size_t)Mm*Dd],  g_Kl[(size_t)Mm*Dd];
__device__ __align__(16) uint16_t g_Vh[(size_t)Mm*Dd],  g_Vl[(size_t)Mm*Dd];
__device__ __align__(16) uint16_t g_Ch[(size_t)Mm*Dd],  g_Cl[(size_t)Mm*Dd];
__device__ __align__(16) uint16_t g_Hh[(size_t)Mm*DFFf], g_Hl[(size_t)Mm*DFFf];
__device__ __align__(16) uint16_t g_Wqh[Ll*Dd*Dd],  g_Wql[Ll*Dd*Dd];
__device__ __align__(16) uint16_t g_Wkh[Ll*Dd*Dd],  g_Wkl[Ll*Dd*Dd];
__device__ __align__(16) uint16_t g_Wvh[Ll*Dd*Dd],  g_Wvl[Ll*Dd*Dd];
__device__ __align__(16) uint16_t g_Woh[Ll*Dd*Dd],  g_Wol[Ll*Dd*Dd];
__device__ __align__(16) uint16_t g_W1h[Ll*Dd*DFFf], g_W1l[Ll*Dd*DFFf];
__device__ __align__(16) uint16_t g_W2h[Ll*DFFf*Dd], g_W2l[Ll*DFFf*Dd];

// ======================= helpers ============================================
__device__ __forceinline__ uint32_t cvta_s(const void* p) {
    return (uint32_t)__cvta_generic_to_shared(p);
}
__device__ __forceinline__ void ldsm4(uint32_t r[4], uint32_t a) {
    asm volatile("ldmatrix.sync.aligned.m8n8.x4.shared.b16 {%0,%1,%2,%3}, [%4];"
        : "=r"(r[0]), "=r"(r[1]), "=r"(r[2]), "=r"(r[3]) : "r"(a));
}
__device__ __forceinline__ void ldsm4t(uint32_t r[4], uint32_t a) {
    asm volatile("ldmatrix.sync.aligned.m8n8.x4.trans.shared.b16 {%0,%1,%2,%3}, [%4];"
        : "=r"(r[0]), "=r"(r[1]), "=r"(r[2]), "=r"(r[3]) : "r"(a));
}
__device__ __forceinline__ void mma_bf(float c[4], const uint32_t a[4],
                                       const uint32_t b[2]) {
    asm volatile(
        "mma.sync.aligned.m16n8k16.row.col.f32.bf16.bf16.f32 "
        "{%0,%1,%2,%3},{%4,%5,%6,%7},{%8,%9},{%0,%1,%2,%3};"
        : "+f"(c[0]), "+f"(c[1]), "+f"(c[2]), "+f"(c[3])
        : "r"(a[0]), "r"(a[1]), "r"(a[2]), "r"(a[3]), "r"(b[0]), "r"(b[1]));
}
__device__ __forceinline__ uint32_t pack_bf(float x, float y) {
    uint32_t r;
    asm("cvt.rn.bf16x2.f32 %0, %1, %2;" : "=r"(r) : "f"(y), "f"(x));
    return r;
}
__device__ __forceinline__ void split_pair(float x, float y,
                                           uint32_t& hi, uint32_t& lo) {
    hi = pack_bf(x, y);
    float hx = __uint_as_float(hi << 16);
    float hy = __uint_as_float(hi & 0xFFFF0000u);
    lo = pack_bf(x - hx, y - hy);
}
#define CPA16(sa, ga) \
    asm volatile("cp.async.cg.shared.global [%0], [%1], 16;" :: "r"(sa), "l"(ga))
#define CP_COMMIT() asm volatile("cp.async.commit_group;")
#define CP_WAIT0()  asm volatile("cp.async.wait_group 0;")
#define CP_WAIT1()  asm volatile("cp.async.wait_group 1;")

// ---------------- converters ------------------------------------------------
__global__ void split_w(const float* __restrict__ in, uint16_t* __restrict__ hi,
                        uint16_t* __restrict__ lo, int n2)
{
    for (int i = blockIdx.x * blockDim.x + threadIdx.x; i < n2;
         i += gridDim.x * blockDim.x) {
        float2 v = ((const float2*)in)[i];
        uint32_t h, l;
        split_pair(v.x, v.y, h, l);
        *(uint32_t*)&hi[2*i] = h;
        *(uint32_t*)&lo[2*i] = l;
    }
}
__global__ void src_conv(const float* __restrict__ in, float* __restrict__ of,
                         uint16_t* __restrict__ hi, uint16_t* __restrict__ lo,
                         int n2)
{
    for (int i = blockIdx.x * blockDim.x + threadIdx.x; i < n2;
         i += gridDim.x * blockDim.x) {
        float2 v = ((const float2*)in)[i];
        ((float2*)of)[i] = v;
        uint32_t h, l;
        split_pair(v.x, v.y, h, l);
        *(uint32_t*)&hi[2*i] = h;
        *(uint32_t*)&lo[2*i] = l;
    }
}

// ============== bf16x3 GEMM: 4 warps, 64x64 warp tile, cp.async x2 ==========
#define APITCH 40
#define BPITCH 136
// dynamic smem layout (halves): Ah buf*5120 | Al 10240+buf*5120 |
//                               Bh 20480+buf*4352 | Bl 29184+buf*4352
#define GSM_HALVES 37888
#define GSM_BYTES  (GSM_HALVES*2)

__device__ __forceinline__ void gemm_load(
    uint32_t sb, int buf, int kt,
    const uint16_t* Ah_, const uint16_t* Al_,
    const uint16_t* Wh_, const uint16_t* Wl_,
    int m0, int n0, int N, int K, int tid)
{
#pragma unroll
    for (int u = 0; u < 16; u++) {
        const int c = u * 128 + tid;
        uint32_t sa; const uint16_t* ga;
        if (u < 8) {              // A tiles: 512 chunks each
            const int cc = c & 511;
            const int r = cc >> 2, c16 = cc & 3;
            const uint16_t* base = (u < 4) ? Ah_ : Al_;
            ga = base + (size_t)(m0 + r) * K + kt + c16 * 8;
            sa = sb + (((u < 4 ? 0 : 10240) + buf*5120 + r*APITCH + c16*8) << 1);
        } else {                  // B tiles
            const int cc = c & 511;
            const int r = cc >> 4, c16 = cc & 15;
            const uint16_t* base = (u < 12) ? Wh_ : Wl_;
            ga = base + (size_t)(kt + r) * N + n0 + c16 * 8;
            sa = sb + (((u < 12 ? 20480 : 29184) + buf*4352 + r*BPITCH + c16*8) << 1);
        }
        CPA16(sa, ga);
    }
}

__global__ __launch_bounds__(128) void gemm_bf(
    const uint16_t* __restrict__ Ah_, const uint16_t* __restrict__ Al_,
    const uint16_t* __restrict__ Wh_, const uint16_t* __restrict__ Wl_,
    const float* __restrict__ bias,
    float* __restrict__ Cf, uint16_t* __restrict__ Ch_, uint16_t* __restrict__ Cl_,
    int N, int K, int act)
{
    extern __shared__ __align__(16) uint16_t dsm[];
    const uint32_t sb = cvta_s(dsm);

    const int tid  = threadIdx.x;
    const int lane = tid & 31, wid = tid >> 5;
    const int wm = wid & 1, wn = wid >> 1;
    const int m0 = blockIdx.y * 128, n0 = blockIdx.x * 128;

    float acc[4][8][4];
#pragma unroll
    for (int i = 0; i < 4; i++)
#pragma unroll
        for (int j = 0; j < 8; j++)
#pragma unroll
            for (int u = 0; u < 4; u++) acc[i][j][u] = 0.f;

    gemm_load(sb, 0, 0, Ah_, Al_, Wh_, Wl_, m0, n0, N, K, tid);
    CP_COMMIT();

    const int mmm = lane >> 3, rr = lane & 7;
    const int niter = K >> 5;

    for (int it = 0; it < niter; it++) {
        const int pb = it & 1;
        if (it + 1 < niter) {
            gemm_load(sb, pb ^ 1, (it + 1) << 5, Ah_, Al_, Wh_, Wl_,
                      m0, n0, N, K, tid);
            CP_COMMIT();
            CP_WAIT1();
        } else {
            CP_WAIT0();
        }
        __syncthreads();

#pragma unroll
        for (int kb = 0; kb < 2; kb++) {
            uint32_t ah[4][4], al[4][4];
#pragma unroll
            for (int i = 0; i < 4; i++) {
                const int row = wm * 64 + i * 16 + (lane & 15);
                const uint32_t ba = sb +
                    ((pb*5120 + row*APITCH + kb*16 + ((lane >> 4) << 3)) << 1);
                ldsm4(ah[i], ba);
                ldsm4(al[i], ba + (10240 << 1));
            }
            const int kk = kb * 16 + ((mmm & 1) << 3) + rr;
#pragma unroll
            for (int jp = 0; jp < 4; jp++) {
                uint32_t bh4[4], bl4[4];
                const int nn = wn * 64 + jp * 16 + ((mmm >> 1) << 3);
                const uint32_t ba = sb +
                    ((20480 + pb*4352 + kk*BPITCH + nn) << 1);
                ldsm4t(bh4, ba);
                ldsm4t(bl4, ba + (8704 << 1));
#pragma unroll
                for (int i = 0; i < 4; i++) {
                    mma_bf(acc[i][2*jp],   ah[i], bh4);
                    mma_bf(acc[i][2*jp],   ah[i], bl4);
                    mma_bf(acc[i][2*jp],   al[i], bh4);
                    mma_bf(acc[i][2*jp+1], ah[i], bh4 + 2);
                    mma_bf(acc[i][2*jp+1], ah[i], bl4 + 2);
                    mma_bf(acc[i][2*jp+1], al[i], bh4 + 2);
                }
            }
        }
        __syncthreads();
    }

    // ---- epilogue ----
    const int gid = lane >> 2, tig = lane & 3;
#pragma unroll
    for (int i = 0; i < 4; i++) {
        const int r0 = m0 + wm * 64 + i * 16 + gid;
#pragma unroll
        for (int j = 0; j < 8; j++) {
            const int col = n0 + wn * 64 + j * 8 + tig * 2;
            const float b0 = bias[col], b1 = bias[col + 1];
            float x0 = acc[i][j][0] + b0, x1 = acc[i][j][1] + b1;
            float x2 = acc[i][j][2] + b0, x3 = acc[i][j][3] + b1;
            if (act) {
                x0 = 0.5f * x0 * (1.f + erff(x0 * 0.70710678118654752f));
                x1 = 0.5f * x1 * (1.f + erff(x1 * 0.70710678118654752f));
                x2 = 0.5f * x2 * (1.f + erff(x2 * 0.70710678118654752f));
                x3 = 0.5f * x3 * (1.f + erff(x3 * 0.70710678118654752f));
            }
            if (Cf) {
                *(float2*)(Cf + (size_t)r0 * N + col)       = make_float2(x0, x1);
                *(float2*)(Cf + (size_t)(r0 + 8) * N + col) = make_float2(x2, x3);
            }
            if (Ch_) {
                uint32_t h, l;
                split_pair(x0, x1, h, l);
                *(uint32_t*)&Ch_[(size_t)r0 * N + col] = h;
                *(uint32_t*)&Cl_[(size_t)r0 * N + col] = l;
                split_pair(x2, x3, h, l);
                *(uint32_t*)&Ch_[(size_t)(r0 + 8) * N + col] = h;
                *(uint32_t*)&Cl_[(size_t)(r0 + 8) * N + col] = l;
            }
        }
    }
}

// ============== flash attention: 4 warps x 32q, cp.async x2, LDG bias =======
#define KPITCH 40
// static smem: 2 buf x {Kh,Kl,Vh,Vl} x 64x40 halves = 40960 B
__global__ __launch_bounds__(128) void attn_mma(
    const uint16_t* __restrict__ Qh_, const uint16_t* __restrict__ Ql_,
    const uint16_t* __restrict__ Kh_, const uint16_t* __restrict__ Kl_,
    const uint16_t* __restrict__ Vh_, const uint16_t* __restrict__ Vl_,
    const float* __restrict__ sph,
    uint16_t* __restrict__ Oh_, uint16_t* __restrict__ Ol_)
{
    __shared__ __align__(16) uint16_t KV[2*4*64*KPITCH];
    const uint32_t sb = cvta_s(KV);

    const int tid  = threadIdx.x;
    const int lane = tid & 31, w = tid >> 5;
    const int gid = lane >> 2, tig = lane & 3;
    const int mmm = lane >> 3, rr = lane & 7;
    const int qt = blockIdx.x, h = blockIdx.y, b = blockIdx.z;
    const int q0 = qt * 128;

    // ---- stage Q (128x32 hi/lo) through smem, extract fragments ----
#pragma unroll
    for (int u = 0; u < 8; u++) {
        const int c = (u * 128 + tid) & 511;
        const int r = c >> 2, c16 = c & 3;
        const uint16_t* base = (u < 4) ? Qh_ : Ql_;
        const uint16_t* ga = base + (size_t)(b*Ss + q0 + r) * Dd + h*32 + c16*8;
        const uint32_t sa = sb + (((u < 4 ? 0 : 5120) + r*KPITCH + c16*8) << 1);
        CPA16(sa, ga);
    }
    CP_COMMIT(); CP_WAIT0();
    __syncthreads();
    uint32_t qh[2][2][4], ql[2][2][4];
#pragma unroll
    for (int rb = 0; rb < 2; rb++)
#pragma unroll
        for (int kb = 0; kb < 2; kb++) {
            const int row = w * 32 + rb * 16 + (lane & 15);
            const uint32_t ba = sb +
                ((row*KPITCH + kb*16 + ((lane >> 4) << 3)) << 1);
            ldsm4(qh[rb][kb], ba);
            ldsm4(ql[rb][kb], ba + (5120 << 1));
        }
    __syncthreads();

    float m[2][2], l[2][2];
#pragma unroll
    for (int rb = 0; rb < 2; rb++) {
        m[rb][0] = m[rb][1] = -INFINITY;
        l[rb][0] = l[rb][1] = 0.f;
    }
    float o[2][4][4];
#pragma unroll
    for (int rb = 0; rb < 2; rb++)
#pragma unroll
        for (int jd = 0; jd < 4; jd++)
#pragma unroll
            for (int u = 0; u < 4; u++) o[rb][jd][u] = 0.f;

    const float* sphb = sph + (size_t)b*Ss*Ss + (size_t)q0*Ss;
    const float sc = 0.17677669529663687f;   // 1/sqrt(32)

    // issue tile 0
#pragma unroll
    for (int u = 0; u < 8; u++) {
        const int c = u * 128 + tid;
        const int t = u >> 1;
        const int cc = c & 255;
        const int r = cc >> 2, c16 = cc & 3;
        const uint16_t* base = (t == 0) ? Kh_ : (t == 1) ? Kl_ :
                               (t == 2) ? Vh_ : Vl_;
        const uint16_t* ga = base + (size_t)(b*Ss + r) * Dd + h*32 + c16*8;
        const uint32_t sa = sb + ((t*2560 + r*KPITCH + c16*8) << 1);
        CPA16(sa, ga);
    }
    CP_COMMIT();

    for (int it = 0; it < Ss/64; it++) {
        const int pb = it & 1;
        const int k0 = it * 64;
        if (it + 1 < Ss/64) {
            const int nk0 = k0 + 64;
#pragma unroll
            for (int u = 0; u < 8; u++) {
                const int c = u * 128 + tid;
                const int t = u >> 1;
                const int cc = c & 255;
                const int r = cc >> 2, c16 = cc & 3;
                const uint16_t* base = (t == 0) ? Kh_ : (t == 1) ? Kl_ :
                                       (t == 2) ? Vh_ : Vl_;
                const uint16_t* ga = base +
                    (size_t)(b*Ss + nk0 + r) * Dd + h*32 + c16*8;
                const uint32_t sa = sb +
                    ((((pb^1)*4 + t)*2560 + r*KPITCH + c16*8) << 1);
                CPA16(sa, ga);
            }
            CP_COMMIT();
            CP_WAIT1();
        } else {
            CP_WAIT0();
        }
        __syncthreads();

        const uint32_t kbase = sb + ((pb*4*2560) << 1);

        // ---- S = Q K^T ----
        float s[2][8][4];
#pragma unroll
        for (int rb = 0; rb < 2; rb++)
#pragma unroll
            for (int j = 0; j < 8; j++)
#pragma unroll
                for (int u = 0; u < 4; u++) s[rb][j][u] = 0.f;

#pragma unroll
        for (int kb = 0; kb < 2; kb++) {
            const int kk = kb * 16 + ((mmm & 1) << 3);
#pragma unroll
            for (int jp = 0; jp < 4; jp++) {
                uint32_t kh4[4], kl4[4];
                const int nn = jp * 16 + ((mmm >> 1) << 3) + rr;
                const uint32_t ba = kbase + ((nn*KPITCH + kk) << 1);
                ldsm4(kh4, ba);
                ldsm4(kl4, ba + (2560 << 1));
#pragma unroll
                for (int rb = 0; rb < 2; rb++) {
                    mma_bf(s[rb][2*jp],   qh[rb][kb], kh4);
                    mma_bf(s[rb][2*jp],   qh[rb][kb], kl4);
                    mma_bf(s[rb][2*jp],   ql[rb][kb], kh4);
                    mma_bf(s[rb][2*jp+1], qh[rb][kb], kh4 + 2);
                    mma_bf(s[rb][2*jp+1], qh[rb][kb], kl4 + 2);
                    mma_bf(s[rb][2*jp+1], ql[rb][kb], kh4 + 2);
                }
            }
        }

        // ---- scale + bias (direct LDG) + online softmax ----
        uint32_t ph[2][4][4], pl[2][4][4];
#pragma unroll
        for (int rb = 0; rb < 2; rb++) {
            const int row0 = w*32 + rb*16 + gid;
            float rmax0 = -INFINITY, rmax1 = -INFINITY;
#pragma unroll
            for (int j = 0; j < 8; j++) {
                const int col = k0 + j * 8 + tig * 2;
                const float2 b0 = __ldg((const float2*)(sphb +
                    (size_t)row0 * Ss + col));
                const float2 b1 = __ldg((const float2*)(sphb +
                    (size_t)(row0 + 8) * Ss + col));
                s[rb][j][0] = fmaf(s[rb][j][0], sc, b0.x);
                s[rb][j][1] = fmaf(s[rb][j][1], sc, b0.y);
                s[rb][j][2] = fmaf(s[rb][j][2], sc, b1.x);
                s[rb][j][3] = fmaf(s[rb][j][3], sc, b1.y);
                rmax0 = fmaxf(rmax0, fmaxf(s[rb][j][0], s[rb][j][1]));
                rmax1 = fmaxf(rmax1, fmaxf(s[rb][j][2], s[rb][j][3]));
            }
            rmax0 = fmaxf(rmax0, __shfl_xor_sync(0xffffffffu, rmax0, 1));
            rmax0 = fmaxf(rmax0, __shfl_xor_sync(0xffffffffu, rmax0, 2));
            rmax1 = fmaxf(rmax1, __shfl_xor_sync(0xffffffffu, rmax1, 1));
            rmax1 = fmaxf(rmax1, __shfl_xor_sync(0xffffffffu, rmax1, 2));

            const float mn0 = fmaxf(m[rb][0], rmax0);
            const float mn1 = fmaxf(m[rb][1], rmax1);
            const float al0 = __expf(m[rb][0] - mn0);
            const float al1 = __expf(m[rb][1] - mn1);
            m[rb][0] = mn0; m[rb][1] = mn1;

            float ps0 = 0.f, ps1 = 0.f;
#pragma unroll
            for (int j = 0; j < 8; j++) {
                float p0 = __expf(s[rb][j][0] - mn0);
                float p1 = __expf(s[rb][j][1] - mn0);
                float p2 = __expf(s[rb][j][2] - mn1);
                float p3 = __expf(s[rb][j][3] - mn1);
                ps0 += p0 + p1; ps1 += p2 + p3;
                uint32_t hA, lA, hB, lB;
                split_pair(p0, p1, hA, lA);
                split_pair(p2, p3, hB, lB);
                const int kb = j >> 1;
                if (!(j & 1)) { ph[rb][kb][0] = hA; pl[rb][kb][0] = lA;
                                ph[rb][kb][1] = hB; pl[rb][kb][1] = lB; }
                else          { ph[rb][kb][2] = hA; pl[rb][kb][2] = lA;
                                ph[rb][kb][3] = hB; pl[rb][kb][3] = lB; }
            }
            ps0 += __shfl_xor_sync(0xffffffffu, ps0, 1);
            ps0 += __shfl_xor_sync(0xffffffffu, ps0, 2);
            ps1 += __shfl_xor_sync(0xffffffffu, ps1, 1);
            ps1 += __shfl_xor_sync(0xffffffffu, ps1, 2);
            l[rb][0] = l[rb][0] * al0 + ps0;
            l[rb][1] = l[rb][1] * al1 + ps1;
#pragma unroll
            for (int jd = 0; jd < 4; jd++) {
                o[rb][jd][0] *= al0; o[rb][jd][1] *= al0;
                o[rb][jd][2] *= al1; o[rb][jd][3] *= al1;
            }
        }

        // ---- O += P V ----
        const uint32_t vbase = kbase + ((2*2560) << 1);
#pragma unroll
        for (int kb = 0; kb < 4; kb++) {
            const int kk = kb * 16 + ((mmm & 1) << 3) + rr;
#pragma unroll
            for (int jp = 0; jp < 2; jp++) {
                uint32_t vh4[4], vl4[4];
                const int dd = jp * 16 + ((mmm >> 1) << 3);
                const uint32_t ba = vbase + ((kk*KPITCH + dd) << 1);
                ldsm4t(vh4, ba);
                ldsm4t(vl4, ba + (2560 << 1));
#pragma unroll
                for (int rb = 0; rb < 2; rb++) {
                    mma_bf(o[rb][2*jp],   ph[rb][kb], vh4);
                    mma_bf(o[rb][2*jp],   ph[rb][kb], vl4);
                    mma_bf(o[rb][2*jp],   pl[rb][kb], vh4);
                    mma_bf(o[rb][2*jp+1], ph[rb][kb], vh4 + 2);
                    mma_bf(o[rb][2*jp+1], ph[rb][kb], vl4 + 2);
                    mma_bf(o[rb][2*jp+1], pl[rb][kb], vh4 + 2);
                }
            }
        }
        __syncthreads();
    }

#pragma unroll
    for (int rb = 0; rb < 2; rb++) {
        const float inv0 = 1.f / l[rb][0], inv1 = 1.f / l[rb][1];
        const int r0 = b*Ss + q0 + w*32 + rb*16 + gid;
#pragma unroll
        for (int jd = 0; jd < 4; jd++) {
            const int col = h * 32 + jd * 8 + tig * 2;
            uint32_t hh, ll2;
            split_pair(o[rb][jd][0] * inv0, o[rb][jd][1] * inv0, hh, ll2);
            *(uint32_t*)&Oh_[(size_t)r0 * Dd + col] = hh;
            *(uint32_t*)&Ol_[(size_t)r0 * Dd + col] = ll2;
            split_pair(o[rb][jd][2] * inv1, o[rb][jd][3] * inv1, hh, ll2);
            *(uint32_t*)&Oh_[(size_t)(r0 + 8) * Dd + col] = hh;
            *(uint32_t*)&Ol_[(size_t)(r0 + 8) * Dd + col] = ll2;
        }
    }
}

// ---------------- fused residual + LayerNorm (+ bf16 mirrors) ---------------
__global__ __launch_bounds__(256) void add_ln(
    const float* __restrict__ x, const float* __restrict__ s,
    const float* __restrict__ g, const float* __restrict__ bb,
    float* __restrict__ out, uint16_t* __restrict__ oh, uint16_t* __restrict__ ol)
{
    const int row = blockIdx.x;
    const int t   = threadIdx.x;
    const size_t idx = (size_t)row * Dd + t;
    const float v = x[idx] + s[idx];

    float sum = v, sq = v * v;
#pragma unroll
    for (int o = 16; o; o >>= 1) {
        sum += __shfl_xor_sync(0xffffffffu, sum, o);
        sq  += __shfl_xor_sync(0xffffffffu, sq,  o);
    }
    __shared__ float ssum[8], ssq[8];
    const int w = t >> 5, lane = t & 31;
    if (lane == 0) { ssum[w] = sum; ssq[w] = sq; }
    __syncthreads();
    if (w == 0) {
        float a = (lane < 8) ? ssum[lane] : 0.f;
        float c = (lane < 8) ? ssq[lane]  : 0.f;
#pragma unroll
        for (int o = 4; o; o >>= 1) {
            a += __shfl_xor_sync(0xffffffffu, a, o);
            c += __shfl_xor_sync(0xffffffffu, c, o);
        }
        if (lane == 0) { ssum[0] = a; ssq[0] = c; }
    }
    __syncthreads();
    const float mu  = ssum[0] * (1.f / Dd);
    const float var = ssq[0]  * (1.f / Dd) - mu * mu;
    const float y = (v - mu) * rsqrtf(var + 1e-5f) * g[t] + bb[t];
    out[idx] = y;
    if (oh) {
        __nv_bfloat16 hb = __float2bfloat16(y);
        float hf = __bfloat162float(hb);
        __nv_bfloat16 lb = __float2bfloat16(y - hf);
        oh[idx] = __bfloat16_as_ushort(hb);
        ol[idx] = __bfloat16_as_ushort(lb);
    }
}

// ---------------- driver ----------------------------------------------------
extern "C" void kernel_launch(void* const* d_in, const int* in_sizes, int n_in,
                              void* d_out, int out_size)
{
    const float* src = (const float*)d_in[0];
    const float* sph = (const float*)d_in[1];
    const float* Wq  = (const float*)d_in[2];
    const float* bq  = (const float*)d_in[3];
    const float* Wk  = (const float*)d_in[4];
    const float* bk  = (const float*)d_in[5];
    const float* Wv  = (const float*)d_in[6];
    const float* bv  = (const float*)d_in[7];
    const float* Wo  = (const float*)d_in[8];
    const float* bo  = (const float*)d_in[9];
    const float* W1  = (const float*)d_in[10];
    const float* b1  = (const float*)d_in[11];
    const float* W2  = (const float*)d_in[12];
    const float* b2  = (const float*)d_in[13];
    const float* g1  = (const float*)d_in[14];
    const float* be1 = (const float*)d_in[15];
    const float* g2  = (const float*)d_in[16];
    const float* be2 = (const float*)d_in[17];
    float* out = (float*)d_out;

    float *X, *Tb;
    uint16_t *Xh,*Xl,*Qh,*Ql,*Kh,*Kl,*Vh,*Vl,*Ch,*Cl,*Hhp,*Hlp;
    uint16_t *Wqh,*Wql,*Wkh,*Wkl,*Wvh,*Wvl,*Woh,*Wol,*W1h,*W1l,*W2h,*W2l;
    cudaGetSymbolAddress((void**)&X,  g_X);
    cudaGetSymbolAddress((void**)&Tb, g_Tb);
    cudaGetSymbolAddress((void**)&Xh, g_Xh); cudaGetSymbolAddress((void**)&Xl, g_Xl);
    cudaGetSymbolAddress((void**)&Qh, g_Qh); cudaGetSymbolAddress((void**)&Ql, g_Ql);
    cudaGetSymbolAddress((void**)&Kh, g_Kh); cudaGetSymbolAddress((void**)&Kl, g_Kl);
    cudaGetSymbolAddress((void**)&Vh, g_Vh); cudaGetSymbolAddress((void**)&Vl, g_Vl);
    cudaGetSymbolAddress((void**)&Ch, g_Ch); cudaGetSymbolAddress((void**)&Cl, g_Cl);
    cudaGetSymbolAddress((void**)&Hhp, g_Hh); cudaGetSymbolAddress((void**)&Hlp, g_Hl);
    cudaGetSymbolAddress((void**)&Wqh, g_Wqh); cudaGetSymbolAddress((void**)&Wql, g_Wql);
    cudaGetSymbolAddress((void**)&Wkh, g_Wkh); cudaGetSymbolAddress((void**)&Wkl, g_Wkl);
    cudaGetSymbolAddress((void**)&Wvh, g_Wvh); cudaGetSymbolAddress((void**)&Wvl, g_Wvl);
    cudaGetSymbolAddress((void**)&Woh, g_Woh); cudaGetSymbolAddress((void**)&Wol, g_Wol);
    cudaGetSymbolAddress((void**)&W1h, g_W1h); cudaGetSymbolAddress((void**)&W1l, g_W1l);
    cudaGetSymbolAddress((void**)&W2h, g_W2h); cudaGetSymbolAddress((void**)&W2l, g_W2l);

    cudaFuncSetAttribute(gemm_bf, cudaFuncAttributeMaxDynamicSharedMemorySize,
                         GSM_BYTES);

    split_w<<<512, 256>>>(Wq, Wqh, Wql, Ll*Dd*Dd/2);
    split_w<<<512, 256>>>(Wk, Wkh, Wkl, Ll*Dd*Dd/2);
    split_w<<<512, 256>>>(Wv, Wvh, Wvl, Ll*Dd*Dd/2);
    split_w<<<512, 256>>>(Wo, Woh, Wol, Ll*Dd*Dd/2);
    split_w<<<1024, 256>>>(W1, W1h, W1l, Ll*Dd*DFFf/2);
    split_w<<<1024, 256>>>(W2, W2h, W2l, Ll*DFFf*Dd/2);
    src_conv<<<1024, 256>>>(src, X, Xh, Xl, Mm*Dd/2);

    const dim3 gD (Dd/128,   Mm/128);   // 2  x 128
    const dim3 gF1(DFFf/128, Mm/128);   // 8  x 128
    const dim3 gAt(Ss/128, Hh, Bb);     // 16 x 8 x 8

    for (int i = 0; i < Ll; i++) {
        const size_t od = (size_t)i*Dd*Dd, of1 = (size_t)i*Dd*DFFf,
                     of2 = (size_t)i*DFFf*Dd;

        gemm_bf<<<gD, 128, GSM_BYTES>>>(Xh, Xl, Wqh+od, Wql+od, bq + i*Dd,
                             nullptr, Qh, Ql, Dd, Dd, 0);
        gemm_bf<<<gD, 128, GSM_BYTES>>>(Xh, Xl, Wkh+od, Wkl+od, bk + i*Dd,
                             nullptr, Kh, Kl, Dd, Dd, 0);
        gemm_bf<<<gD, 128, GSM_BYTES>>>(Xh, Xl, Wvh+od, Wvl+od, bv + i*Dd,
                             nullptr, Vh, Vl, Dd, Dd, 0);

        attn_mma<<<gAt, 128>>>(Qh, Ql, Kh, Kl, Vh, Vl, sph, Ch, Cl);

        gemm_bf<<<gD, 128, GSM_BYTES>>>(Ch, Cl, Woh+od, Wol+od, bo + i*Dd,
                             Tb, nullptr, nullptr, Dd, Dd, 0);
        add_ln<<<Mm, Dd>>>(X, Tb, g1 + i*Dd, be1 + i*Dd, X, Xh, Xl);

        gemm_bf<<<gF1, 128, GSM_BYTES>>>(Xh, Xl, W1h+of1, W1l+of1, b1 + i*DFFf,
                              nullptr, Hhp, Hlp, DFFf, Dd, 1);
        gemm_bf<<<gD, 128, GSM_BYTES>>>(Hhp, Hlp, W2h+of2, W2l+of2, b2 + i*Dd,
                             Tb, nullptr, nullptr, Dd, DFFf, 0);
        if (i == Ll-1)
            add_ln<<<Mm, Dd>>>(X, Tb, g2 + i*Dd, be2 + i*Dd, out,
                               nullptr, nullptr);
        else
            add_ln<<<Mm, Dd>>>(X, Tb, g2 + i*Dd, be2 + i*Dd, X, Xh, Xl);
    }
}

// round 10
// speedup vs baseline: 1.2901x; 1.0575x over previous
#include <cuda_runtime.h>
#include <cuda_bf16.h>
#include <cuda_fp16.h>
#include <math.h>
#include <stdint.h>

#define Bb   8
#define Ss   2048
#define Dd   256
#define Hh   8
#define DKk  32
#define DFFf 1024
#define Ll   5
#define Mm   (Bb*Ss)   // 16384 rows
#define QS   768       // QKV fused row stride

// ---------------- scratch (device globals; no allocation allowed) ----------
__device__ float g_X [(size_t)Mm*Dd];
__device__ float g_Tb[(size_t)Mm*Dd];
__device__ __align__(16) uint16_t g_Xh[(size_t)Mm*Dd],  g_Xl[(size_t)Mm*Dd];
__device__ __align__(16) uint16_t g_QKVh[(size_t)Mm*QS], g_QKVl[(size_t)Mm*QS];
__device__ __align__(16) uint16_t g_Ch[(size_t)Mm*Dd],  g_Cl[(size_t)Mm*Dd];
__device__ __align__(16) uint16_t g_Hh[(size_t)Mm*DFFf], g_Hl[(size_t)Mm*DFFf];
__device__ __align__(16) __half  g_sph[(size_t)Bb*Ss*Ss];
__device__ __align__(16) uint16_t g_Wqkvh[Ll*Dd*QS], g_Wqkvl[Ll*Dd*QS];
__device__ float g_bqkv[Ll*QS];
__device__ __align__(16) uint16_t g_Woh[Ll*Dd*Dd],  g_Wol[Ll*Dd*Dd];
__device__ __align__(16) uint16_t g_W1h[Ll*Dd*DFFf], g_W1l[Ll*Dd*DFFf];
__device__ __align__(16) uint16_t g_W2h[Ll*DFFf*Dd], g_W2l[Ll*DFFf*Dd];

// ======================= helpers ============================================
__device__ __forceinline__ uint32_t cvta_s(const void* p) {
    return (uint32_t)__cvta_generic_to_shared(p);
}
__device__ __forceinline__ void ldsm4(uint32_t r[4], uint32_t a) {
    asm volatile("ldmatrix.sync.aligned.m8n8.x4.shared.b16 {%0,%1,%2,%3}, [%4];"
        : "=r"(r[0]), "=r"(r[1]), "=r"(r[2]), "=r"(r[3]) : "r"(a));
}
__device__ __forceinline__ void ldsm4t(uint32_t r[4], uint32_t a) {
    asm volatile("ldmatrix.sync.aligned.m8n8.x4.trans.shared.b16 {%0,%1,%2,%3}, [%4];"
        : "=r"(r[0]), "=r"(r[1]), "=r"(r[2]), "=r"(r[3]) : "r"(a));
}
__device__ __forceinline__ void mma_bf(float c[4], const uint32_t a[4],
                                       const uint32_t b[2]) {
    asm volatile(
        "mma.sync.aligned.m16n8k16.row.col.f32.bf16.bf16.f32 "
        "{%0,%1,%2,%3},{%4,%5,%6,%7},{%8,%9},{%0,%1,%2,%3};"
        : "+f"(c[0]), "+f"(c[1]), "+f"(c[2]), "+f"(c[3])
        : "r"(a[0]), "r"(a[1]), "r"(a[2]), "r"(a[3]), "r"(b[0]), "r"(b[1]));
}
__device__ __forceinline__ uint32_t pack_bf(float x, float y) {
    uint32_t r;
    asm("cvt.rn.bf16x2.f32 %0, %1, %2;" : "=r"(r) : "f"(y), "f"(x));
    return r;
}
__device__ __forceinline__ void split_pair(float x, float y,
                                           uint32_t& hi, uint32_t& lo) {
    hi = pack_bf(x, y);
    float hx = __uint_as_float(hi << 16);
    float hy = __uint_as_float(hi & 0xFFFF0000u);
    lo = pack_bf(x - hx, y - hy);
}
__device__ __forceinline__ float ex2(float x) {
    float y; asm("ex2.approx.ftz.f32 %0, %1;" : "=f"(y) : "f"(x));
    return y;
}
#define CPA16(sa, ga) \
    asm volatile("cp.async.cg.shared.global [%0], [%1], 16;" :: "r"(sa), "l"(ga))
#define CP_COMMIT() asm volatile("cp.async.commit_group;")
#define CP_WAIT0()  asm volatile("cp.async.wait_group 0;")
#define CP_WAIT1()  asm volatile("cp.async.wait_group 1;")

// ---------------- converters ------------------------------------------------
__global__ void split_w(const float* __restrict__ in, uint16_t* __restrict__ hi,
                        uint16_t* __restrict__ lo, int n2)
{
    for (int i = blockIdx.x * blockDim.x + threadIdx.x; i < n2;
         i += gridDim.x * blockDim.x) {
        float2 v = ((const float2*)in)[i];
        uint32_t h, l;
        split_pair(v.x, v.y, h, l);
        *(uint32_t*)&hi[2*i] = h;
        *(uint32_t*)&lo[2*i] = l;
    }
}
// Wq/Wk/Wv [Ll,256,256] -> concatenated [Ll,256,768] at column offset col0
__global__ void split_wcat(const float* __restrict__ in,
                           uint16_t* __restrict__ hi, uint16_t* __restrict__ lo,
                           int col0)
{
    const int n2 = Ll * Dd * (Dd/2);
    for (int i = blockIdx.x * blockDim.x + threadIdx.x; i < n2;
         i += gridDim.x * blockDim.x) {
        const int lk = i >> 7, c2 = i & 127;              // row (l*256+k), col pair
        float2 v = ((const float2*)in)[i];
        uint32_t h, l;
        split_pair(v.x, v.y, h, l);
        const size_t o = (size_t)lk * QS + col0 + c2 * 2;
        *(uint32_t*)&hi[o] = h;
        *(uint32_t*)&lo[o] = l;
    }
}
__global__ void cat_bias(const float* __restrict__ bq, const float* __restrict__ bk,
                         const float* __restrict__ bv, float* __restrict__ dst)
{
    const int i = blockIdx.x * blockDim.x + threadIdx.x;   // Ll*QS threads
    if (i >= Ll * QS) return;
    const int l = i / QS, n = i % QS;
    dst[i] = (n < 256) ? bq[l*256 + n]
           : (n < 512) ? bk[l*256 + n - 256]
                       : bv[l*256 + n - 512];
}
__global__ void sph_conv(const float* __restrict__ in, __half* __restrict__ out)
{
    const float lg2e = 1.4426950408889634f;
    const int n = Bb * Ss * Ss / 2;
    for (int i = blockIdx.x * blockDim.x + threadIdx.x; i < n;
         i += gridDim.x * blockDim.x) {
        float2 v = ((const float2*)in)[i];
        ((__half2*)out)[i] = __floats2half2_rn(v.x * lg2e, v.y * lg2e);
    }
}
__global__ void src_conv(const float* __restrict__ in, float* __restrict__ of,
                         uint16_t* __restrict__ hi, uint16_t* __restrict__ lo,
                         int n2)
{
    for (int i = blockIdx.x * blockDim.x + threadIdx.x; i < n2;
         i += gridDim.x * blockDim.x) {
        float2 v = ((const float2*)in)[i];
        ((float2*)of)[i] = v;
        uint32_t h, l;
        split_pair(v.x, v.y, h, l);
        *(uint32_t*)&hi[2*i] = h;
        *(uint32_t*)&lo[2*i] = l;
    }
}

// ============== bf16x3 GEMM: 4 warps, 64x64 warp tile, cp.async x2 ==========
#define APITCH 40
#define BPITCH 136
#define GSM_HALVES 37888
#define GSM_BYTES  (GSM_HALVES*2)

__device__ __forceinline__ void gemm_load(
    uint32_t sb, int buf, int kt,
    const uint16_t* Ah_, const uint16_t* Al_,
    const uint16_t* Wh_, const uint16_t* Wl_,
    int m0, int n0, int N, int K, int tid)
{
#pragma unroll
    for (int u = 0; u < 16; u++) {
        const int c = u * 128 + tid;
        uint32_t sa; const uint16_t* ga;
        if (u < 8) {
            const int cc = c & 511;
            const int r = cc >> 2, c16 = cc & 3;
            const uint16_t* base = (u < 4) ? Ah_ : Al_;
            ga = base + (size_t)(m0 + r) * K + kt + c16 * 8;
            sa = sb + (((u < 4 ? 0 : 10240) + buf*5120 + r*APITCH + c16*8) << 1);
        } else {
            const int cc = c & 511;
            const int r = cc >> 4, c16 = cc & 15;
            const uint16_t* base = (u < 12) ? Wh_ : Wl_;
            ga = base + (size_t)(kt + r) * N + n0 + c16 * 8;
            sa = sb + (((u < 12 ? 20480 : 29184) + buf*4352 + r*BPITCH + c16*8) << 1);
        }
        CPA16(sa, ga);
    }
}

__global__ __launch_bounds__(128) void gemm_bf(
    const uint16_t* __restrict__ Ah_, const uint16_t* __restrict__ Al_,
    const uint16_t* __restrict__ Wh_, const uint16_t* __restrict__ Wl_,
    const float* __restrict__ bias,
    float* __restrict__ Cf, uint16_t* __restrict__ Ch_, uint16_t* __restrict__ Cl_,
    int N, int K, int act)
{
    extern __shared__ __align__(16) uint16_t dsm[];
    const uint32_t sb = cvta_s(dsm);

    const int tid  = threadIdx.x;
    const int lane = tid & 31, wid = tid >> 5;
    const int wm = wid & 1, wn = wid >> 1;
    const int m0 = blockIdx.y * 128, n0 = blockIdx.x * 128;

    float acc[4][8][4];
#pragma unroll
    for (int i = 0; i < 4; i++)
#pragma unroll
        for (int j = 0; j < 8; j++)
#pragma unroll
            for (int u = 0; u < 4; u++) acc[i][j][u] = 0.f;

    gemm_load(sb, 0, 0, Ah_, Al_, Wh_, Wl_, m0, n0, N, K, tid);
    CP_COMMIT();

    const int mmm = lane >> 3, rr = lane & 7;
    const int niter = K >> 5;

    for (int it = 0; it < niter; it++) {
        const int pb = it & 1;
        if (it + 1 < niter) {
            gemm_load(sb, pb ^ 1, (it + 1) << 5, Ah_, Al_, Wh_, Wl_,
                      m0, n0, N, K, tid);
            CP_COMMIT();
            CP_WAIT1();
        } else {
            CP_WAIT0();
        }
        __syncthreads();

#pragma unroll
        for (int kb = 0; kb < 2; kb++) {
            uint32_t ah[4][4], al[4][4];
#pragma unroll
            for (int i = 0; i < 4; i++) {
                const int row = wm * 64 + i * 16 + (lane & 15);
                const uint32_t ba = sb +
                    ((pb*5120 + row*APITCH + kb*16 + ((lane >> 4) << 3)) << 1);
                ldsm4(ah[i], ba);
                ldsm4(al[i], ba + (10240 << 1));
            }
            const int kk = kb * 16 + ((mmm & 1) << 3) + rr;
#pragma unroll
            for (int jp = 0; jp < 4; jp++) {
                uint32_t bh4[4], bl4[4];
                const int nn = wn * 64 + jp * 16 + ((mmm >> 1) << 3);
                const uint32_t ba = sb +
                    ((20480 + pb*4352 + kk*BPITCH + nn) << 1);
                ldsm4t(bh4, ba);
                ldsm4t(bl4, ba + (8704 << 1));
#pragma unroll
                for (int i = 0; i < 4; i++) {
                    mma_bf(acc[i][2*jp],   ah[i], bh4);
                    mma_bf(acc[i][2*jp],   ah[i], bl4);
                    mma_bf(acc[i][2*jp],   al[i], bh4);
                    mma_bf(acc[i][2*jp+1], ah[i], bh4 + 2);
                    mma_bf(acc[i][2*jp+1], ah[i], bl4 + 2);
                    mma_bf(acc[i][2*jp+1], al[i], bh4 + 2);
                }
            }
        }
        __syncthreads();
    }

    const int gid = lane >> 2, tig = lane & 3;
#pragma unroll
    for (int i = 0; i < 4; i++) {
        const int r0 = m0 + wm * 64 + i * 16 + gid;
#pragma unroll
        for (int j = 0; j < 8; j++) {
            const int col = n0 + wn * 64 + j * 8 + tig * 2;
            const float b0 = bias[col], b1 = bias[col + 1];
            float x0 = acc[i][j][0] + b0, x1 = acc[i][j][1] + b1;
            float x2 = acc[i][j][2] + b0, x3 = acc[i][j][3] + b1;
            if (act) {
                x0 = 0.5f * x0 * (1.f + erff(x0 * 0.70710678118654752f));
                x1 = 0.5f * x1 * (1.f + erff(x1 * 0.70710678118654752f));
                x2 = 0.5f * x2 * (1.f + erff(x2 * 0.70710678118654752f));
                x3 = 0.5f * x3 * (1.f + erff(x3 * 0.70710678118654752f));
            }
            if (Cf) {
                *(float2*)(Cf + (size_t)r0 * N + col)       = make_float2(x0, x1);
                *(float2*)(Cf + (size_t)(r0 + 8) * N + col) = make_float2(x2, x3);
            }
            if (Ch_) {
                uint32_t h, l;
                split_pair(x0, x1, h, l);
                *(uint32_t*)&Ch_[(size_t)r0 * N + col] = h;
                *(uint32_t*)&Cl_[(size_t)r0 * N + col] = l;
                split_pair(x2, x3, h, l);
                *(uint32_t*)&Ch_[(size_t)(r0 + 8) * N + col] = h;
                *(uint32_t*)&Cl_[(size_t)(r0 + 8) * N + col] = l;
            }
        }
    }
}

// ============== flash attention: fp16 bias, exp2 softmax, QKV strided =======
#define KPITCH 40
__global__ __launch_bounds__(128) void attn_mma(
    const uint16_t* __restrict__ Qh_, const uint16_t* __restrict__ Ql_,
    const uint16_t* __restrict__ Kh_, const uint16_t* __restrict__ Kl_,
    const uint16_t* __restrict__ Vh_, const uint16_t* __restrict__ Vl_,
    const __half* __restrict__ sph,
    uint16_t* __restrict__ Oh_, uint16_t* __restrict__ Ol_)
{
    __shared__ __align__(16) uint16_t KV[2*4*64*KPITCH];
    const uint32_t sb = cvta_s(KV);

    const int tid  = threadIdx.x;
    const int lane = tid & 31, w = tid >> 5;
    const int gid = lane >> 2, tig = lane & 3;
    const int mmm = lane >> 3, rr = lane & 7;
    const int qt = blockIdx.x, h = blockIdx.y, b = blockIdx.z;
    const int q0 = qt * 128;

#pragma unroll
    for (int u = 0; u < 8; u++) {
        const int c = (u * 128 + tid) & 511;
        const int r = c >> 2, c16 = c & 3;
        const uint16_t* base = (u < 4) ? Qh_ : Ql_;
        const uint16_t* ga = base + (size_t)(b*Ss + q0 + r) * QS + h*32 + c16*8;
        const uint32_t sa = sb + (((u < 4 ? 0 : 5120) + r*KPITCH + c16*8) << 1);
        CPA16(sa, ga);
    }
    CP_COMMIT(); CP_WAIT0();
    __syncthreads();
    uint32_t qh[2][2][4], ql[2][2][4];
#pragma unroll
    for (int rb = 0; rb < 2; rb++)
#pragma unroll
        for (int kb = 0; kb < 2; kb++) {
            const int row = w * 32 + rb * 16 + (lane & 15);
            const uint32_t ba = sb +
                ((row*KPITCH + kb*16 + ((lane >> 4) << 3)) << 1);
            ldsm4(qh[rb][kb], ba);
            ldsm4(ql[rb][kb], ba + (5120 << 1));
        }
    __syncthreads();

    float m[2][2], l[2][2];
#pragma unroll
    for (int rb = 0; rb < 2; rb++) {
        m[rb][0] = m[rb][1] = -INFINITY;
        l[rb][0] = l[rb][1] = 0.f;
    }
    float o[2][4][4];
#pragma unroll
    for (int rb = 0; rb < 2; rb++)
#pragma unroll
        for (int jd = 0; jd < 4; jd++)
#pragma unroll
            for (int u = 0; u < 4; u++) o[rb][jd][u] = 0.f;

    const __half* sphb = sph + (size_t)b*Ss*Ss + (size_t)q0*Ss;
    // scale * log2(e): scores kept in log2 domain
    const float sc = 0.17677669529663687f * 1.4426950408889634f;

#pragma unroll
    for (int u = 0; u < 8; u++) {
        const int c = u * 128 + tid;
        const int t = u >> 1;
        const int cc = c & 255;
        const int r = cc >> 2, c16 = cc & 3;
        const uint16_t* base = (t == 0) ? Kh_ : (t == 1) ? Kl_ :
                               (t == 2) ? Vh_ : Vl_;
        const uint16_t* ga = base + (size_t)(b*Ss + r) * QS + h*32 + c16*8;
        const uint32_t sa = sb + ((t*2560 + r*KPITCH + c16*8) << 1);
        CPA16(sa, ga);
    }
    CP_COMMIT();

    for (int it = 0; it < Ss/64; it++) {
        const int pb = it & 1;
        const int k0 = it * 64;
        if (it + 1 < Ss/64) {
            const int nk0 = k0 + 64;
#pragma unroll
            for (int u = 0; u < 8; u++) {
                const int c = u * 128 + tid;
                const int t = u >> 1;
                const int cc = c & 255;
                const int r = cc >> 2, c16 = cc & 3;
                const uint16_t* base = (t == 0) ? Kh_ : (t == 1) ? Kl_ :
                                       (t == 2) ? Vh_ : Vl_;
                const uint16_t* ga = base +
                    (size_t)(b*Ss + nk0 + r) * QS + h*32 + c16*8;
                const uint32_t sa = sb +
                    ((((pb^1)*4 + t)*2560 + r*KPITCH + c16*8) << 1);
                CPA16(sa, ga);
            }
            CP_COMMIT();
            CP_WAIT1();
        } else {
            CP_WAIT0();
        }
        __syncthreads();

        const uint32_t kbase = sb + ((pb*4*2560) << 1);

        float s[2][8][4];
#pragma unroll
        for (int rb = 0; rb < 2; rb++)
#pragma unroll
            for (int j = 0; j < 8; j++)
#pragma unroll
                for (int u = 0; u < 4; u++) s[rb][j][u] = 0.f;

#pragma unroll
        for (int kb = 0; kb < 2; kb++) {
            const int kk = kb * 16 + ((mmm & 1) << 3);
#pragma unroll
            for (int jp = 0; jp < 4; jp++) {
                uint32_t kh4[4], kl4[4];
                const int nn = jp * 16 + ((mmm >> 1) << 3) + rr;
                const uint32_t ba = kbase + ((nn*KPITCH + kk) << 1);
                ldsm4(kh4, ba);
                ldsm4(kl4, ba + (2560 << 1));
#pragma unroll
                for (int rb = 0; rb < 2; rb++) {
                    mma_bf(s[rb][2*jp],   qh[rb][kb], kh4);
                    mma_bf(s[rb][2*jp],   qh[rb][kb], kl4);
                    mma_bf(s[rb][2*jp],   ql[rb][kb], kh4);
                    mma_bf(s[rb][2*jp+1], qh[rb][kb], kh4 + 2);
                    mma_bf(s[rb][2*jp+1], qh[rb][kb], kl4 + 2);
                    mma_bf(s[rb][2*jp+1], ql[rb][kb], kh4 + 2);
                }
            }
        }

        uint32_t ph[2][4][4], pl[2][4][4];
#pragma unroll
        for (int rb = 0; rb < 2; rb++) {
            const int row0 = w*32 + rb*16 + gid;
            float rmax0 = -INFINITY, rmax1 = -INFINITY;
#pragma unroll
            for (int j = 0; j < 8; j++) {
                const int col = k0 + j * 8 + tig * 2;
                const float2 b0 = __half22float2(
                    *(const __half2*)(sphb + (size_t)row0 * Ss + col));
                const float2 b1 = __half22float2(
                    *(const __half2*)(sphb + (size_t)(row0 + 8) * Ss + col));
                s[rb][j][0] = fmaf(s[rb][j][0], sc, b0.x);
                s[rb][j][1] = fmaf(s[rb][j][1], sc, b0.y);
                s[rb][j][2] = fmaf(s[rb][j][2], sc, b1.x);
                s[rb][j][3] = fmaf(s[rb][j][3], sc, b1.y);
                rmax0 = fmaxf(rmax0, fmaxf(s[rb][j][0], s[rb][j][1]));
                rmax1 = fmaxf(rmax1, fmaxf(s[rb][j][2], s[rb][j][3]));
            }
            rmax0 = fmaxf(rmax0, __shfl_xor_sync(0xffffffffu, rmax0, 1));
            rmax0 = fmaxf(rmax0, __shfl_xor_sync(0xffffffffu, rmax0, 2));
            rmax1 = fmaxf(rmax1, __shfl_xor_sync(0xffffffffu, rmax1, 1));
            rmax1 = fmaxf(rmax1, __shfl_xor_sync(0xffffffffu, rmax1, 2));

            const float mn0 = fmaxf(m[rb][0], rmax0);
            const float mn1 = fmaxf(m[rb][1], rmax1);
            const float al0 = ex2(m[rb][0] - mn0);
            const float al1 = ex2(m[rb][1] - mn1);
            m[rb][0] = mn0; m[rb][1] = mn1;

            float ps0 = 0.f, ps1 = 0.f;
#pragma unroll
            for (int j = 0; j < 8; j++) {
                float p0 = ex2(s[rb][j][0] - mn0);
                float p1 = ex2(s[rb][j][1] - mn0);
                float p2 = ex2(s[rb][j][2] - mn1);
                float p3 = ex2(s[rb][j][3] - mn1);
                ps0 += p0 + p1; ps1 += p2 + p3;
                uint32_t hA, lA, hB, lB;
                split_pair(p0, p1, hA, lA);
                split_pair(p2, p3, hB, lB);
                const int kb = j >> 1;
                if (!(j & 1)) { ph[rb][kb][0] = hA; pl[rb][kb][0] = lA;
                                ph[rb][kb][1] = hB; pl[rb][kb][1] = lB; }
                else          { ph[rb][kb][2] = hA; pl[rb][kb][2] = lA;
                                ph[rb][kb][3] = hB; pl[rb][kb][3] = lB; }
            }
            ps0 += __shfl_xor_sync(0xffffffffu, ps0, 1);
            ps0 += __shfl_xor_sync(0xffffffffu, ps0, 2);
            ps1 += __shfl_xor_sync(0xffffffffu, ps1, 1);
            ps1 += __shfl_xor_sync(0xffffffffu, ps1, 2);
            l[rb][0] = l[rb][0] * al0 + ps0;
            l[rb][1] = l[rb][1] * al1 + ps1;
#pragma unroll
            for (int jd = 0; jd < 4; jd++) {
                o[rb][jd][0] *= al0; o[rb][jd][1] *= al0;
                o[rb][jd][2] *= al1; o[rb][jd][3] *= al1;
            }
        }

        const uint32_t vbase = kbase + ((2*2560) << 1);
#pragma unroll
        for (int kb = 0; kb < 4; kb++) {
            const int kk = kb * 16 + ((mmm & 1) << 3) + rr;
#pragma unroll
            for (int jp = 0; jp < 2; jp++) {
                uint32_t vh4[4], vl4[4];
                const int dd = jp * 16 + ((mmm >> 1) << 3);
                const uint32_t ba = vbase + ((kk*KPITCH + dd) << 1);
                ldsm4t(vh4, ba);
                ldsm4t(vl4, ba + (2560 << 1));
#pragma unroll
                for (int rb = 0; rb < 2; rb++) {
                    mma_bf(o[rb][2*jp],   ph[rb][kb], vh4);
                    mma_bf(o[rb][2*jp],   ph[rb][kb], vl4);
                    mma_bf(o[rb][2*jp],   pl[rb][kb], vh4);
                    mma_bf(o[rb][2*jp+1], ph[rb][kb], vh4 + 2);
                    mma_bf(o[rb][2*jp+1], ph[rb][kb], vl4 + 2);
                    mma_bf(o[rb][2*jp+1], pl[rb][kb], vh4 + 2);
                }
            }
        }
        __syncthreads();
    }

#pragma unroll
    for (int rb = 0; rb < 2; rb++) {
        const float inv0 = 1.f / l[rb][0], inv1 = 1.f / l[rb][1];
        const int r0 = b*Ss + q0 + w*32 + rb*16 + gid;
#pragma unroll
        for (int jd = 0; jd < 4; jd++) {
            const int col = h * 32 + jd * 8 + tig * 2;
            uint32_t hh, ll2;
            split_pair(o[rb][jd][0] * inv0, o[rb][jd][1] * inv0, hh, ll2);
            *(uint32_t*)&Oh_[(size_t)r0 * Dd + col] = hh;
            *(uint32_t*)&Ol_[(size_t)r0 * Dd + col] = ll2;
            split_pair(o[rb][jd][2] * inv1, o[rb][jd][3] * inv1, hh, ll2);
            *(uint32_t*)&Oh_[(size_t)(r0 + 8) * Dd + col] = hh;
            *(uint32_t*)&Ol_[(size_t)(r0 + 8) * Dd + col] = ll2;
        }
    }
}

// ---------------- fused residual + LayerNorm (+ bf16 mirrors) ---------------
__global__ __launch_bounds__(256) void add_ln(
    const float* __restrict__ x, const float* __restrict__ s,
    const float* __restrict__ g, const float* __restrict__ bb,
    float* __restrict__ out, uint16_t* __restrict__ oh, uint16_t* __restrict__ ol)
{
    const int row = blockIdx.x;
    const int t   = threadIdx.x;
    const size_t idx = (size_t)row * Dd + t;
    const float v = x[idx] + s[idx];

    float sum = v, sq = v * v;
#pragma unroll
    for (int o = 16; o; o >>= 1) {
        sum += __shfl_xor_sync(0xffffffffu, sum, o);
        sq  += __shfl_xor_sync(0xffffffffu, sq,  o);
    }
    __shared__ float ssum[8], ssq[8];
    const int w = t >> 5, lane = t & 31;
    if (lane == 0) { ssum[w] = sum; ssq[w] = sq; }
    __syncthreads();
    if (w == 0) {
        float a = (lane < 8) ? ssum[lane] : 0.f;
        float c = (lane < 8) ? ssq[lane]  : 0.f;
#pragma unroll
        for (int o = 4; o; o >>= 1) {
            a += __shfl_xor_sync(0xffffffffu, a, o);
            c += __shfl_xor_sync(0xffffffffu, c, o);
        }
        if (lane == 0) { ssum[0] = a; ssq[0] = c; }
    }
    __syncthreads();
    const float mu  = ssum[0] * (1.f / Dd);
    const float var = ssq[0]  * (1.f / Dd) - mu * mu;
    const float y = (v - mu) * rsqrtf(var + 1e-5f) * g[t] + bb[t];
    out[idx] = y;
    if (oh) {
        __nv_bfloat16 hb = __float2bfloat16(y);
        float hf = __bfloat162float(hb);
        __nv_bfloat16 lb = __float2bfloat16(y - hf);
        oh[idx] = __bfloat16_as_ushort(hb);
        ol[idx] = __bfloat16_as_ushort(lb);
    }
}

// ---------------- driver ----------------------------------------------------
extern "C" void kernel_launch(void* const* d_in, const int* in_sizes, int n_in,
                              void* d_out, int out_size)
{
    const float* src = (const float*)d_in[0];
    const float* sph = (const float*)d_in[1];
    const float* Wq  = (const float*)d_in[2];
    const float* bq  = (const float*)d_in[3];
    const float* Wk  = (const float*)d_in[4];
    const float* bk  = (const float*)d_in[5];
    const float* Wv  = (const float*)d_in[6];
    const float* bv  = (const float*)d_in[7];
    const float* Wo  = (const float*)d_in[8];
    const float* bo  = (const float*)d_in[9];
    const float* W1  = (const float*)d_in[10];
    const float* b1  = (const float*)d_in[11];
    const float* W2  = (const float*)d_in[12];
    const float* b2  = (const float*)d_in[13];
    const float* g1  = (const float*)d_in[14];
    const float* be1 = (const float*)d_in[15];
    const float* g2  = (const float*)d_in[16];
    const float* be2 = (const float*)d_in[17];
    float* out = (float*)d_out;

    float *X, *Tb, *bqkv;
    uint16_t *Xh,*Xl,*QKVh,*QKVl,*Ch,*Cl,*Hhp,*Hlp;
    uint16_t *Wch,*Wcl,*Woh,*Wol,*W1h,*W1l,*W2h,*W2l;
    __half *sphH;
    cudaGetSymbolAddress((void**)&X,  g_X);
    cudaGetSymbolAddress((void**)&Tb, g_Tb);
    cudaGetSymbolAddress((void**)&Xh, g_Xh); cudaGetSymbolAddress((void**)&Xl, g_Xl);
    cudaGetSymbolAddress((void**)&QKVh, g_QKVh);
    cudaGetSymbolAddress((void**)&QKVl, g_QKVl);
    cudaGetSymbolAddress((void**)&Ch, g_Ch); cudaGetSymbolAddress((void**)&Cl, g_Cl);
    cudaGetSymbolAddress((void**)&Hhp, g_Hh); cudaGetSymbolAddress((void**)&Hlp, g_Hl);
    cudaGetSymbolAddress((void**)&Wch, g_Wqkvh);
    cudaGetSymbolAddress((void**)&Wcl, g_Wqkvl);
    cudaGetSymbolAddress((void**)&bqkv, g_bqkv);
    cudaGetSymbolAddress((void**)&Woh, g_Woh); cudaGetSymbolAddress((void**)&Wol, g_Wol);
    cudaGetSymbolAddress((void**)&W1h, g_W1h); cudaGetSymbolAddress((void**)&W1l, g_W1l);
    cudaGetSymbolAddress((void**)&W2h, g_W2h); cudaGetSymbolAddress((void**)&W2l, g_W2l);
    cudaGetSymbolAddress((void**)&sphH, g_sph);

    cudaFuncSetAttribute(gemm_bf, cudaFuncAttributeMaxDynamicSharedMemorySize,
                         GSM_BYTES);

    split_wcat<<<512, 256>>>(Wq, Wch, Wcl, 0);
    split_wcat<<<512, 256>>>(Wk, Wch, Wcl, 256);
    split_wcat<<<512, 256>>>(Wv, Wch, Wcl, 512);
    cat_bias<<<(Ll*QS + 255)/256, 256>>>(bq, bk, bv, bqkv);
    split_w<<<512, 256>>>(Wo, Woh, Wol, Ll*Dd*Dd/2);
    split_w<<<1024, 256>>>(W1, W1h, W1l, Ll*Dd*DFFf/2);
    split_w<<<1024, 256>>>(W2, W2h, W2l, Ll*DFFf*Dd/2);
    sph_conv<<<2048, 256>>>(sph, sphH);
    src_conv<<<1024, 256>>>(src, X, Xh, Xl, Mm*Dd/2);

    const dim3 gQKV(QS/128,  Mm/128);   // 6  x 128
    const dim3 gD (Dd/128,   Mm/128);   // 2  x 128
    const dim3 gF1(DFFf/128, Mm/128);   // 8  x 128
    const dim3 gAt(Ss/128, Hh, Bb);     // 16 x 8 x 8

    for (int i = 0; i < Ll; i++) {
        const size_t od = (size_t)i*Dd*Dd, of1 = (size_t)i*Dd*DFFf,
                     of2 = (size_t)i*DFFf*Dd, oc = (size_t)i*Dd*QS;

        gemm_bf<<<gQKV, 128, GSM_BYTES>>>(Xh, Xl, Wch+oc, Wcl+oc, bqkv + i*QS,
                             nullptr, QKVh, QKVl, QS, Dd, 0);

        attn_mma<<<gAt, 128>>>(QKVh, QKVl, QKVh + 256, QKVl + 256,
                               QKVh + 512, QKVl + 512, sphH, Ch, Cl);

        gemm_bf<<<gD, 128, GSM_BYTES>>>(Ch, Cl, Woh+od, Wol+od, bo + i*Dd,
                             Tb, nullptr, nullptr, Dd, Dd, 0);
        add_ln<<<Mm, Dd>>>(X, Tb, g1 + i*Dd, be1 + i*Dd, X, Xh, Xl);

        gemm_bf<<<gF1, 128, GSM_BYTES>>>(Xh, Xl, W1h+of1, W1l+of1, b1 + i*DFFf,
                              nullptr, Hhp, Hlp, DFFf, Dd, 1);
        gemm_bf<<<gD, 128, GSM_BYTES>>>(Hhp, Hlp, W2h+of2, W2l+of2, b2 + i*Dd,
                             Tb, nullptr, nullptr, Dd, DFFf, 0);
        if (i == Ll-1)
            add_ln<<<Mm, Dd>>>(X, Tb, g2 + i*Dd, be2 + i*Dd, out,
                               nullptr, nullptr);
        else
            add_ln<<<Mm, Dd>>>(X, Tb, g2 + i*Dd, be2 + i*Dd, X, Xh, Xl);
    }
}

// round 16
// speedup vs baseline: 1.6380x; 1.2696x over previous
#include <cuda_runtime.h>
#include <cuda_bf16.h>
#include <cuda_fp16.h>
#include <math.h>
#include <stdint.h>

#define Bb   8
#define Ss   2048
#define Dd   256
#define Hh   8
#define DKk  32
#define DFFf 1024
#define Ll   5
#define Mm   (Bb*Ss)   // 16384 rows
#define QS   768       // QKV fused row stride

// ---------------- scratch (device globals; no allocation allowed) ----------
__device__ float g_X [(size_t)Mm*Dd];
__device__ float g_Tb[(size_t)Mm*Dd];
__device__ __align__(16) uint16_t g_Xh[(size_t)Mm*Dd],  g_Xl[(size_t)Mm*Dd];
__device__ __align__(16) __half  g_QKVf[(size_t)Mm*QS];
__device__ __align__(16) uint16_t g_Ch[(size_t)Mm*Dd],  g_Cl[(size_t)Mm*Dd];
__device__ __align__(16) uint16_t g_Hh[(size_t)Mm*DFFf], g_Hl[(size_t)Mm*DFFf];
__device__ __align__(16) __half  g_sph[(size_t)Bb*Ss*Ss];
__device__ __align__(16) uint16_t g_Wqkvh[Ll*Dd*QS], g_Wqkvl[Ll*Dd*QS];
__device__ float g_bqkv[Ll*QS];
__device__ __align__(16) uint16_t g_Woh[Ll*Dd*Dd],  g_Wol[Ll*Dd*Dd];
__device__ __align__(16) uint16_t g_W1h[Ll*Dd*DFFf], g_W1l[Ll*Dd*DFFf];
__device__ __align__(16) uint16_t g_W2h[Ll*DFFf*Dd], g_W2l[Ll*DFFf*Dd];

// ======================= helpers ============================================
__device__ __forceinline__ uint32_t cvta_s(const void* p) {
    return (uint32_t)__cvta_generic_to_shared(p);
}
__device__ __forceinline__ void ldsm4(uint32_t r[4], uint32_t a) {
    asm volatile("ldmatrix.sync.aligned.m8n8.x4.shared.b16 {%0,%1,%2,%3}, [%4];"
        : "=r"(r[0]), "=r"(r[1]), "=r"(r[2]), "=r"(r[3]) : "r"(a));
}
__device__ __forceinline__ void ldsm4t(uint32_t r[4], uint32_t a) {
    asm volatile("ldmatrix.sync.aligned.m8n8.x4.trans.shared.b16 {%0,%1,%2,%3}, [%4];"
        : "=r"(r[0]), "=r"(r[1]), "=r"(r[2]), "=r"(r[3]) : "r"(a));
}
__device__ __forceinline__ void mma_bf(float c[4], const uint32_t a[4],
                                       const uint32_t b[2]) {
    asm volatile(
        "mma.sync.aligned.m16n8k16.row.col.f32.bf16.bf16.f32 "
        "{%0,%1,%2,%3},{%4,%5,%6,%7},{%8,%9},{%0,%1,%2,%3};"
        : "+f"(c[0]), "+f"(c[1]), "+f"(c[2]), "+f"(c[3])
        : "r"(a[0]), "r"(a[1]), "r"(a[2]), "r"(a[3]), "r"(b[0]), "r"(b[1]));
}
__device__ __forceinline__ void mma_fp(float c[4], const uint32_t a[4],
                                       const uint32_t b[2]) {
    asm volatile(
        "mma.sync.aligned.m16n8k16.row.col.f32.f16.f16.f32 "
        "{%0,%1,%2,%3},{%4,%5,%6,%7},{%8,%9},{%0,%1,%2,%3};"
        : "+f"(c[0]), "+f"(c[1]), "+f"(c[2]), "+f"(c[3])
        : "r"(a[0]), "r"(a[1]), "r"(a[2]), "r"(a[3]), "r"(b[0]), "r"(b[1]));
}
__device__ __forceinline__ uint32_t pack_bf(float x, float y) {
    uint32_t r;
    asm("cvt.rn.bf16x2.f32 %0, %1, %2;" : "=r"(r) : "f"(y), "f"(x));
    return r;
}
__device__ __forceinline__ uint32_t pack_fp(float x, float y) {
    uint32_t r;
    asm("cvt.rn.f16x2.f32 %0, %1, %2;" : "=r"(r) : "f"(y), "f"(x));
    return r;
}
__device__ __forceinline__ void split_pair(float x, float y,
                                           uint32_t& hi, uint32_t& lo) {
    hi = pack_bf(x, y);
    float hx = __uint_as_float(hi << 16);
    float hy = __uint_as_float(hi & 0xFFFF0000u);
    lo = pack_bf(x - hx, y - hy);
}
__device__ __forceinline__ float ex2(float x) {
    float y; asm("ex2.approx.ftz.f32 %0, %1;" : "=f"(y) : "f"(x));
    return y;
}
#define CPA16(sa, ga) \
    asm volatile("cp.async.cg.shared.global [%0], [%1], 16;" :: "r"(sa), "l"(ga))
#define CP_COMMIT() asm volatile("cp.async.commit_group;")
#define CP_WAIT0()  asm volatile("cp.async.wait_group 0;")
#define CP_WAIT1()  asm volatile("cp.async.wait_group 1;")

// ---------------- converters ------------------------------------------------
__global__ void split_w(const float* __restrict__ in, uint16_t* __restrict__ hi,
                        uint16_t* __restrict__ lo, int n2)
{
    for (int i = blockIdx.x * blockDim.x + threadIdx.x; i < n2;
         i += gridDim.x * blockDim.x) {
        float2 v = ((const float2*)in)[i];
        uint32_t h, l;
        split_pair(v.x, v.y, h, l);
        *(uint32_t*)&hi[2*i] = h;
        *(uint32_t*)&lo[2*i] = l;
    }
}
__global__ void split_wcat(const float* __restrict__ in,
                           uint16_t* __restrict__ hi, uint16_t* __restrict__ lo,
                           int col0)
{
    const int n2 = Ll * Dd * (Dd/2);
    for (int i = blockIdx.x * blockDim.x + threadIdx.x; i < n2;
         i += gridDim.x * blockDim.x) {
        const int lk = i >> 7, c2 = i & 127;
        float2 v = ((const float2*)in)[i];
        uint32_t h, l;
        split_pair(v.x, v.y, h, l);
        const size_t o = (size_t)lk * QS + col0 + c2 * 2;
        *(uint32_t*)&hi[o] = h;
        *(uint32_t*)&lo[o] = l;
    }
}
__global__ void cat_bias(const float* __restrict__ bq, const float* __restrict__ bk,
                         const float* __restrict__ bv, float* __restrict__ dst)
{
    const int i = blockIdx.x * blockDim.x + threadIdx.x;
    if (i >= Ll * QS) return;
    const int l = i / QS, n = i % QS;
    dst[i] = (n < 256) ? bq[l*256 + n]
           : (n < 512) ? bk[l*256 + n - 256]
                       : bv[l*256 + n - 512];
}
__global__ void sph_conv(const float* __restrict__ in, __half* __restrict__ out)
{
    const float lg2e = 1.4426950408889634f;
    const int n = Bb * Ss * Ss / 2;
    for (int i = blockIdx.x * blockDim.x + threadIdx.x; i < n;
         i += gridDim.x * blockDim.x) {
        float2 v = ((const float2*)in)[i];
        ((__half2*)out)[i] = __floats2half2_rn(v.x * lg2e, v.y * lg2e);
    }
}
__global__ void src_conv(const float* __restrict__ in, float* __restrict__ of,
                         uint16_t* __restrict__ hi, uint16_t* __restrict__ lo,
                         int n2)
{
    for (int i = blockIdx.x * blockDim.x + threadIdx.x; i < n2;
         i += gridDim.x * blockDim.x) {
        float2 v = ((const float2*)in)[i];
        ((float2*)of)[i] = v;
        uint32_t h, l;
        split_pair(v.x, v.y, h, l);
        *(uint32_t*)&hi[2*i] = h;
        *(uint32_t*)&lo[2*i] = l;
    }
}

// ============== bf16x3 GEMM: 4 warps, 64x64 warp tile, cp.async x2 ==========
#define APITCH 40
#define BPITCH 136
#define GSM_HALVES 37888
#define GSM_BYTES  (GSM_HALVES*2)

__device__ __forceinline__ void gemm_load(
    uint32_t sb, int buf, int kt,
    const uint16_t* Ah_, const uint16_t* Al_,
    const uint16_t* Wh_, const uint16_t* Wl_,
    int m0, int n0, int N, int K, int tid)
{
#pragma unroll
    for (int u = 0; u < 16; u++) {
        const int c = u * 128 + tid;
        uint32_t sa; const uint16_t* ga;
        if (u < 8) {
            const int cc = c & 511;
            const int r = cc >> 2, c16 = cc & 3;
            const uint16_t* base = (u < 4) ? Ah_ : Al_;
            ga = base + (size_t)(m0 + r) * K + kt + c16 * 8;
            sa = sb + (((u < 4 ? 0 : 10240) + buf*5120 + r*APITCH + c16*8) << 1);
        } else {
            const int cc = c & 511;
            const int r = cc >> 4, c16 = cc & 15;
            const uint16_t* base = (u < 12) ? Wh_ : Wl_;
            ga = base + (size_t)(kt + r) * N + n0 + c16 * 8;
            sa = sb + (((u < 12 ? 20480 : 29184) + buf*4352 + r*BPITCH + c16*8) << 1);
        }
        CPA16(sa, ga);
    }
}

__global__ __launch_bounds__(128) void gemm_bf(
    const uint16_t* __restrict__ Ah_, const uint16_t* __restrict__ Al_,
    const uint16_t* __restrict__ Wh_, const uint16_t* __restrict__ Wl_,
    const float* __restrict__ bias,
    float* __restrict__ Cf, uint16_t* __restrict__ Ch_, uint16_t* __restrict__ Cl_,
    __half* __restrict__ Cfp,
    int N, int K, int act)
{
    extern __shared__ __align__(16) uint16_t dsm[];
    const uint32_t sb = cvta_s(dsm);

    const int tid  = threadIdx.x;
    const int lane = tid & 31, wid = tid >> 5;
    const int wm = wid & 1, wn = wid >> 1;
    const int m0 = blockIdx.y * 128, n0 = blockIdx.x * 128;

    float acc[4][8][4];
#pragma unroll
    for (int i = 0; i < 4; i++)
#pragma unroll
        for (int j = 0; j < 8; j++)
#pragma unroll
            for (int u = 0; u < 4; u++) acc[i][j][u] = 0.f;

    gemm_load(sb, 0, 0, Ah_, Al_, Wh_, Wl_, m0, n0, N, K, tid);
    CP_COMMIT();

    const int mmm = lane >> 3, rr = lane & 7;
    const int niter = K >> 5;

    for (int it = 0; it < niter; it++) {
        const int pb = it & 1;
        if (it + 1 < niter) {
            gemm_load(sb, pb ^ 1, (it + 1) << 5, Ah_, Al_, Wh_, Wl_,
                      m0, n0, N, K, tid);
            CP_COMMIT();
            CP_WAIT1();
        } else {
            CP_WAIT0();
        }
        __syncthreads();

#pragma unroll
        for (int kb = 0; kb < 2; kb++) {
            uint32_t ah[4][4], al[4][4];
#pragma unroll
            for (int i = 0; i < 4; i++) {
                const int row = wm * 64 + i * 16 + (lane & 15);
                const uint32_t ba = sb +
                    ((pb*5120 + row*APITCH + kb*16 + ((lane >> 4) << 3)) << 1);
                ldsm4(ah[i], ba);
                ldsm4(al[i], ba + (10240 << 1));
            }
            const int kk = kb * 16 + ((mmm & 1) << 3) + rr;
#pragma unroll
            for (int jp = 0; jp < 4; jp++) {
                uint32_t bh4[4], bl4[4];
                const int nn = wn * 64 + jp * 16 + ((mmm >> 1) << 3);
                const uint32_t ba = sb +
                    ((20480 + pb*4352 + kk*BPITCH + nn) << 1);
                ldsm4t(bh4, ba);
                ldsm4t(bl4, ba + (8704 << 1));
#pragma unroll
                for (int i = 0; i < 4; i++) {
                    mma_bf(acc[i][2*jp],   ah[i], bh4);
                    mma_bf(acc[i][2*jp],   ah[i], bl4);
                    mma_bf(acc[i][2*jp],   al[i], bh4);
                    mma_bf(acc[i][2*jp+1], ah[i], bh4 + 2);
                    mma_bf(acc[i][2*jp+1], ah[i], bl4 + 2);
                    mma_bf(acc[i][2*jp+1], al[i], bh4 + 2);
                }
            }
        }
        __syncthreads();
    }

    const int gid = lane >> 2, tig = lane & 3;
#pragma unroll
    for (int i = 0; i < 4; i++) {
        const int r0 = m0 + wm * 64 + i * 16 + gid;
#pragma unroll
        for (int j = 0; j < 8; j++) {
            const int col = n0 + wn * 64 + j * 8 + tig * 2;
            const float b0 = bias[col], b1 = bias[col + 1];
            float x0 = acc[i][j][0] + b0, x1 = acc[i][j][1] + b1;
            float x2 = acc[i][j][2] + b0, x3 = acc[i][j][3] + b1;
            if (act) {
                x0 = 0.5f * x0 * (1.f + erff(x0 * 0.70710678118654752f));
                x1 = 0.5f * x1 * (1.f + erff(x1 * 0.70710678118654752f));
                x2 = 0.5f * x2 * (1.f + erff(x2 * 0.70710678118654752f));
                x3 = 0.5f * x3 * (1.f + erff(x3 * 0.70710678118654752f));
            }
            if (Cf) {
                *(float2*)(Cf + (size_t)r0 * N + col)       = make_float2(x0, x1);
                *(float2*)(Cf + (size_t)(r0 + 8) * N + col) = make_float2(x2, x3);
            }
            if (Cfp) {
                *(uint32_t*)(Cfp + (size_t)r0 * N + col)       = pack_fp(x0, x1);
                *(uint32_t*)(Cfp + (size_t)(r0 + 8) * N + col) = pack_fp(x2, x3);
            }
            if (Ch_) {
                uint32_t h, l;
                split_pair(x0, x1, h, l);
                *(uint32_t*)&Ch_[(size_t)r0 * N + col] = h;
                *(uint32_t*)&Cl_[(size_t)r0 * N + col] = l;
                split_pair(x2, x3, h, l);
                *(uint32_t*)&Ch_[(size_t)(r0 + 8) * N + col] = h;
                *(uint32_t*)&Cl_[(size_t)(r0 + 8) * N + col] = l;
            }
        }
    }
}

// ============== flash attention: full fp16 inputs, fp32 accum ===============
#define KPITCH 40
// smem: 2 buf x {K,V} x 64x40 halves = 10240 halves = 20 KB (Q staged in buf0)
__global__ __launch_bounds__(128) void attn_mma(
    const __half* __restrict__ Qf_, const __half* __restrict__ Kf_,
    const __half* __restrict__ Vf_,
    const __half* __restrict__ sph,
    uint16_t* __restrict__ Oh_, uint16_t* __restrict__ Ol_)
{
    __shared__ __align__(16) uint16_t KV[2*2*64*KPITCH];
    const uint32_t sb = cvta_s(KV);

    const int tid  = threadIdx.x;
    const int lane = tid & 31, w = tid >> 5;
    const int gid = lane >> 2, tig = lane & 3;
    const int mmm = lane >> 3, rr = lane & 7;
    const int qt = blockIdx.x, h = blockIdx.y, b = blockIdx.z;
    const int q0 = qt * 128;

    // ---- stage Q (128x32 fp16) into buf0 region, extract fragments ----
#pragma unroll
    for (int u = 0; u < 4; u++) {
        const int c = u * 128 + tid;                 // 512 chunks
        const int r = c >> 2, c16 = c & 3;
        const __half* ga = Qf_ + (size_t)(b*Ss + q0 + r) * QS + h*32 + c16*8;
        const uint32_t sa = sb + ((r*KPITCH + c16*8) << 1);
        CPA16(sa, ga);
    }
    CP_COMMIT(); CP_WAIT0();
    __syncthreads();
    uint32_t qf[2][2][4];
#pragma unroll
    for (int rb = 0; rb < 2; rb++)
#pragma unroll
        for (int kb = 0; kb < 2; kb++) {
            const int row = w * 32 + rb * 16 + (lane & 15);
            const uint32_t ba = sb +
                ((row*KPITCH + kb*16 + ((lane >> 4) << 3)) << 1);
            ldsm4(qf[rb][kb], ba);
        }
    __syncthreads();

    float m[2][2], l[2][2];
#pragma unroll
    for (int rb = 0; rb < 2; rb++) {
        m[rb][0] = m[rb][1] = -INFINITY;
        l[rb][0] = l[rb][1] = 0.f;
    }
    float o[2][4][4];
#pragma unroll
    for (int rb = 0; rb < 2; rb++)
#pragma unroll
        for (int jd = 0; jd < 4; jd++)
#pragma unroll
            for (int u = 0; u < 4; u++) o[rb][jd][u] = 0.f;

    const __half* sphb = sph + (size_t)b*Ss*Ss + (size_t)q0*Ss;
    const float sc = 0.17677669529663687f * 1.4426950408889634f;

    // issue K/V tile 0 into buf0
#pragma unroll
    for (int u = 0; u < 4; u++) {
        const int c = u * 128 + tid;
        const int t = u >> 1;                        // 0:K 1:V
        const int cc = c & 255;
        const int r = cc >> 2, c16 = cc & 3;
        const __half* base = (t == 0) ? Kf_ : Vf_;
        const __half* ga = base + (size_t)(b*Ss + r) * QS + h*32 + c16*8;
        const uint32_t sa = sb + ((t*2560 + r*KPITCH + c16*8) << 1);
        CPA16(sa, ga);
    }
    CP_COMMIT();

    for (int it = 0; it < Ss/64; it++) {
        const int pb = it & 1;
        const int k0 = it * 64;
        if (it + 1 < Ss/64) {
            const int nk0 = k0 + 64;
#pragma unroll
            for (int u = 0; u < 4; u++) {
                const int c = u * 128 + tid;
                const int t = u >> 1;
                const int cc = c & 255;
                const int r = cc >> 2, c16 = cc & 3;
                const __half* base = (t == 0) ? Kf_ : Vf_;
                const __half* ga = base +
                    (size_t)(b*Ss + nk0 + r) * QS + h*32 + c16*8;
                const uint32_t sa = sb +
                    ((((pb^1)*2 + t)*2560 + r*KPITCH + c16*8) << 1);
                CPA16(sa, ga);
            }
            CP_COMMIT();
            CP_WAIT1();
        } else {
            CP_WAIT0();
        }
        __syncthreads();

        const uint32_t kbase = sb + ((pb*2*2560) << 1);
        const uint32_t vbase = kbase + (2560 << 1);

        // ---- S = Q K^T (single fp16 MMA) ----
        float s[2][8][4];
#pragma unroll
        for (int rb = 0; rb < 2; rb++)
#pragma unroll
            for (int j = 0; j < 8; j++)
#pragma unroll
                for (int u = 0; u < 4; u++) s[rb][j][u] = 0.f;

#pragma unroll
        for (int kb = 0; kb < 2; kb++) {
            const int kk = kb * 16 + ((mmm & 1) << 3);
#pragma unroll
            for (int jp = 0; jp < 4; jp++) {
                uint32_t kf4[4];
                const int nn = jp * 16 + ((mmm >> 1) << 3) + rr;
                ldsm4(kf4, kbase + ((nn*KPITCH + kk) << 1));
#pragma unroll
                for (int rb = 0; rb < 2; rb++) {
                    mma_fp(s[rb][2*jp],   qf[rb][kb], kf4);
                    mma_fp(s[rb][2*jp+1], qf[rb][kb], kf4 + 2);
                }
            }
        }

        // ---- scale + bias + online softmax (log2 domain) ----
        uint32_t ph[2][4][4];
#pragma unroll
        for (int rb = 0; rb < 2; rb++) {
            const int row0 = w*32 + rb*16 + gid;
            float rmax0 = -INFINITY, rmax1 = -INFINITY;
#pragma unroll
            for (int j = 0; j < 8; j++) {
                const int col = k0 + j * 8 + tig * 2;
                const float2 b0 = __half22float2(
                    *(const __half2*)(sphb + (size_t)row0 * Ss + col));
                const float2 b1 = __half22float2(
                    *(const __half2*)(sphb + (size_t)(row0 + 8) * Ss + col));
                s[rb][j][0] = fmaf(s[rb][j][0], sc, b0.x);
                s[rb][j][1] = fmaf(s[rb][j][1], sc, b0.y);
                s[rb][j][2] = fmaf(s[rb][j][2], sc, b1.x);
                s[rb][j][3] = fmaf(s[rb][j][3], sc, b1.y);
                rmax0 = fmaxf(rmax0, fmaxf(s[rb][j][0], s[rb][j][1]));
                rmax1 = fmaxf(rmax1, fmaxf(s[rb][j][2], s[rb][j][3]));
            }
            rmax0 = fmaxf(rmax0, __shfl_xor_sync(0xffffffffu, rmax0, 1));
            rmax0 = fmaxf(rmax0, __shfl_xor_sync(0xffffffffu, rmax0, 2));
            rmax1 = fmaxf(rmax1, __shfl_xor_sync(0xffffffffu, rmax1, 1));
            rmax1 = fmaxf(rmax1, __shfl_xor_sync(0xffffffffu, rmax1, 2));

            const float mn0 = fmaxf(m[rb][0], rmax0);
            const float mn1 = fmaxf(m[rb][1], rmax1);
            const float al0 = ex2(m[rb][0] - mn0);
            const float al1 = ex2(m[rb][1] - mn1);
            m[rb][0] = mn0; m[rb][1] = mn1;

            float ps0 = 0.f, ps1 = 0.f;
#pragma unroll
            for (int j = 0; j < 8; j++) {
                float p0 = ex2(s[rb][j][0] - mn0);
                float p1 = ex2(s[rb][j][1] - mn0);
                float p2 = ex2(s[rb][j][2] - mn1);
                float p3 = ex2(s[rb][j][3] - mn1);
                ps0 += p0 + p1; ps1 += p2 + p3;
                const uint32_t hA = pack_fp(p0, p1);
                const uint32_t hB = pack_fp(p2, p3);
                const int kb = j >> 1;
                if (!(j & 1)) { ph[rb][kb][0] = hA; ph[rb][kb][1] = hB; }
                else          { ph[rb][kb][2] = hA; ph[rb][kb][3] = hB; }
            }
            ps0 += __shfl_xor_sync(0xffffffffu, ps0, 1);
            ps0 += __shfl_xor_sync(0xffffffffu, ps0, 2);
            ps1 += __shfl_xor_sync(0xffffffffu, ps1, 1);
            ps1 += __shfl_xor_sync(0xffffffffu, ps1, 2);
            l[rb][0] = l[rb][0] * al0 + ps0;
            l[rb][1] = l[rb][1] * al1 + ps1;
#pragma unroll
            for (int jd = 0; jd < 4; jd++) {
                o[rb][jd][0] *= al0; o[rb][jd][1] *= al0;
                o[rb][jd][2] *= al1; o[rb][jd][3] *= al1;
            }
        }

        // ---- O += P V (single fp16 MMA) ----
#pragma unroll
        for (int kb = 0; kb < 4; kb++) {
            const int kk = kb * 16 + ((mmm & 1) << 3) + rr;
#pragma unroll
            for (int jp = 0; jp < 2; jp++) {
                uint32_t vf4[4];
                const int dd = jp * 16 + ((mmm >> 1) << 3);
                ldsm4t(vf4, vbase + ((kk*KPITCH + dd) << 1));
#pragma unroll
                for (int rb = 0; rb < 2; rb++) {
                    mma_fp(o[rb][2*jp],   ph[rb][kb], vf4);
                    mma_fp(o[rb][2*jp+1], ph[rb][kb], vf4 + 2);
                }
            }
        }
        __syncthreads();
    }

#pragma unroll
    for (int rb = 0; rb < 2; rb++) {
        const float inv0 = 1.f / l[rb][0], inv1 = 1.f / l[rb][1];
        const int r0 = b*Ss + q0 + w*32 + rb*16 + gid;
#pragma unroll
        for (int jd = 0; jd < 4; jd++) {
            const int col = h * 32 + jd * 8 + tig * 2;
            uint32_t hh, ll2;
            split_pair(o[rb][jd][0] * inv0, o[rb][jd][1] * inv0, hh, ll2);
            *(uint32_t*)&Oh_[(size_t)r0 * Dd + col] = hh;
            *(uint32_t*)&Ol_[(size_t)r0 * Dd + col] = ll2;
            split_pair(o[rb][jd][2] * inv1, o[rb][jd][3] * inv1, hh, ll2);
            *(uint32_t*)&Oh_[(size_t)(r0 + 8) * Dd + col] = hh;
            *(uint32_t*)&Ol_[(size_t)(r0 + 8) * Dd + col] = ll2;
        }
    }
}

// ---------------- fused residual + LayerNorm (+ bf16 mirrors) ---------------
__global__ __launch_bounds__(256) void add_ln(
    const float* __restrict__ x, const float* __restrict__ s,
    const float* __restrict__ g, const float* __restrict__ bb,
    float* __restrict__ out, uint16_t* __restrict__ oh, uint16_t* __restrict__ ol)
{
    const int row = blockIdx.x;
    const int t   = threadIdx.x;
    const size_t idx = (size_t)row * Dd + t;
    const float v = x[idx] + s[idx];

    float sum = v, sq = v * v;
#pragma unroll
    for (int o = 16; o; o >>= 1) {
        sum += __shfl_xor_sync(0xffffffffu, sum, o);
        sq  += __shfl_xor_sync(0xffffffffu, sq,  o);
    }
    __shared__ float ssum[8], ssq[8];
    const int w = t >> 5, lane = t & 31;
    if (lane == 0) { ssum[w] = sum; ssq[w] = sq; }
    __syncthreads();
    if (w == 0) {
        float a = (lane < 8) ? ssum[lane] : 0.f;
        float c = (lane < 8) ? ssq[lane]  : 0.f;
#pragma unroll
        for (int o = 4; o; o >>= 1) {
            a += __shfl_xor_sync(0xffffffffu, a, o);
            c += __shfl_xor_sync(0xffffffffu, c, o);
        }
        if (lane == 0) { ssum[0] = a; ssq[0] = c; }
    }
    __syncthreads();
    const float mu  = ssum[0] * (1.f / Dd);
    const float var = ssq[0]  * (1.f / Dd) - mu * mu;
    const float y = (v - mu) * rsqrtf(var + 1e-5f) * g[t] + bb[t];
    out[idx] = y;
    if (oh) {
        __nv_bfloat16 hb = __float2bfloat16(y);
        float hf = __bfloat162float(hb);
        __nv_bfloat16 lb = __float2bfloat16(y - hf);
        oh[idx] = __bfloat16_as_ushort(hb);
        ol[idx] = __bfloat16_as_ushort(lb);
    }
}

// ---------------- driver ----------------------------------------------------
extern "C" void kernel_launch(void* const* d_in, const int* in_sizes, int n_in,
                              void* d_out, int out_size)
{
    const float* src = (const float*)d_in[0];
    const float* sph = (const float*)d_in[1];
    const float* Wq  = (const float*)d_in[2];
    const float* bq  = (const float*)d_in[3];
    const float* Wk  = (const float*)d_in[4];
    const float* bk  = (const float*)d_in[5];
    const float* Wv  = (const float*)d_in[6];
    const float* bv  = (const float*)d_in[7];
    const float* Wo  = (const float*)d_in[8];
    const float* bo  = (const float*)d_in[9];
    const float* W1  = (const float*)d_in[10];
    const float* b1  = (const float*)d_in[11];
    const float* W2  = (const float*)d_in[12];
    const float* b2  = (const float*)d_in[13];
    const float* g1  = (const float*)d_in[14];
    const float* be1 = (const float*)d_in[15];
    const float* g2  = (const float*)d_in[16];
    const float* be2 = (const float*)d_in[17];
    float* out = (float*)d_out;

    float *X, *Tb, *bqkv;
    uint16_t *Xh,*Xl,*Ch,*Cl,*Hhp,*Hlp;
    uint16_t *Wch,*Wcl,*Woh,*Wol,*W1h,*W1l,*W2h,*W2l;
    __half *sphH, *QKVf;
    cudaGetSymbolAddress((void**)&X,  g_X);
    cudaGetSymbolAddress((void**)&Tb, g_Tb);
    cudaGetSymbolAddress((void**)&Xh, g_Xh); cudaGetSymbolAddress((void**)&Xl, g_Xl);
    cudaGetSymbolAddress((void**)&QKVf, g_QKVf);
    cudaGetSymbolAddress((void**)&Ch, g_Ch); cudaGetSymbolAddress((void**)&Cl, g_Cl);
    cudaGetSymbolAddress((void**)&Hhp, g_Hh); cudaGetSymbolAddress((void**)&Hlp, g_Hl);
    cudaGetSymbolAddress((void**)&Wch, g_Wqkvh);
    cudaGetSymbolAddress((void**)&Wcl, g_Wqkvl);
    cudaGetSymbolAddress((void**)&bqkv, g_bqkv);
    cudaGetSymbolAddress((void**)&Woh, g_Woh); cudaGetSymbolAddress((void**)&Wol, g_Wol);
    cudaGetSymbolAddress((void**)&W1h, g_W1h); cudaGetSymbolAddress((void**)&W1l, g_W1l);
    cudaGetSymbolAddress((void**)&W2h, g_W2h); cudaGetSymbolAddress((void**)&W2l, g_W2l);
    cudaGetSymbolAddress((void**)&sphH, g_sph);

    cudaFuncSetAttribute(gemm_bf, cudaFuncAttributeMaxDynamicSharedMemorySize,
                         GSM_BYTES);

    split_wcat<<<512, 256>>>(Wq, Wch, Wcl, 0);
    split_wcat<<<512, 256>>>(Wk, Wch, Wcl, 256);
    split_wcat<<<512, 256>>>(Wv, Wch, Wcl, 512);
    cat_bias<<<(Ll*QS + 255)/256, 256>>>(bq, bk, bv, bqkv);
    split_w<<<512, 256>>>(Wo, Woh, Wol, Ll*Dd*Dd/2);
    split_w<<<1024, 256>>>(W1, W1h, W1l, Ll*Dd*DFFf/2);
    split_w<<<1024, 256>>>(W2, W2h, W2l, Ll*DFFf*Dd/2);
    sph_conv<<<2048, 256>>>(sph, sphH);
    src_conv<<<1024, 256>>>(src, X, Xh, Xl, Mm*Dd/2);

    const dim3 gQKV(QS/128,  Mm/128);   // 6  x 128
    const dim3 gD (Dd/128,   Mm/128);   // 2  x 128
    const dim3 gF1(DFFf/128, Mm/128);   // 8  x 128
    const dim3 gAt(Ss/128, Hh, Bb);     // 16 x 8 x 8

    for (int i = 0; i < Ll; i++) {
        const size_t od = (size_t)i*Dd*Dd, of1 = (size_t)i*Dd*DFFf,
                     of2 = (size_t)i*DFFf*Dd, oc = (size_t)i*Dd*QS;

        gemm_bf<<<gQKV, 128, GSM_BYTES>>>(Xh, Xl, Wch+oc, Wcl+oc, bqkv + i*QS,
                             nullptr, nullptr, nullptr, QKVf, QS, Dd, 0);

        attn_mma<<<gAt, 128>>>(QKVf, QKVf + 256, QKVf + 512, sphH, Ch, Cl);

        gemm_bf<<<gD, 128, GSM_BYTES>>>(Ch, Cl, Woh+od, Wol+od, bo + i*Dd,
                             Tb, nullptr, nullptr, nullptr, Dd, Dd, 0);
        add_ln<<<Mm, Dd>>>(X, Tb, g1 + i*Dd, be1 + i*Dd, X, Xh, Xl);

        gemm_bf<<<gF1, 128, GSM_BYTES>>>(Xh, Xl, W1h+of1, W1l+of1, b1 + i*DFFf,
                              nullptr, Hhp, Hlp, nullptr, DFFf, Dd, 1);
        gemm_bf<<<gD, 128, GSM_BYTES>>>(Hhp, Hlp, W2h+of2, W2l+of2, b2 + i*Dd,
                             Tb, nullptr, nullptr, nullptr, Dd, DFFf, 0);
        if (i == Ll-1)
            add_ln<<<Mm, Dd>>>(X, Tb, g2 + i*Dd, be2 + i*Dd, out,
                               nullptr, nullptr);
        else
            add_ln<<<Mm, Dd>>>(X, Tb, g2 + i*Dd, be2 + i*Dd, X, Xh, Xl);
    }
}